// round 1
// baseline (speedup 1.0000x reference)
#include <cuda_runtime.h>
#include <math.h>

#define Bn 8
#define Ln 4096
#define Dn 1024
#define Hn 16
#define DHn 64
#define O3 3072

// -------- scratch (static device globals; no allocation) --------
__device__ float g_qkv[(size_t)Bn * O3 * Ln];        // 402 MB: q|k|v, layout (B, 3072, L)
__device__ float g_ctx[Bn * Hn * DHn * DHn];         // 2 MB:  (B,H,64,64)
__device__ float g_weff[Bn * Dn * Dn];               // 33 MB: (B,1024,1024)
__device__ int   g_mask_u8;

// -------- mask dtype detection (bool-u8 vs int32) --------
__global__ void detect_mask_kernel(const unsigned char* __restrict__ m) {
    __shared__ int found;
    if (threadIdx.x == 0) found = 0;
    __syncthreads();
    int local = 0;
    for (int i = threadIdx.x; i < 4096; i += blockDim.x) {
        if ((i & 3) && m[i]) local = 1;
    }
    if (local) atomicOr(&found, 1);
    __syncthreads();
    if (threadIdx.x == 0) g_mask_u8 = found;   // nonzero at non-word-aligned byte => u8 layout
}

__device__ __forceinline__ bool mask_at(const void* m, int idx, int u8) {
    if (u8) return ((const unsigned char*)m)[idx] != 0;
    return ((const int*)m)[idx] != 0;
}

// -------- K1: qkv = w_qkv @ (masked x^T), scale q rows by d^-0.5 --------
// C(3072 x 4096) per batch. Tiles 128x128x8, 256 threads, 8x8 microtile.
__global__ __launch_bounds__(256) void qkv_kernel(const float* __restrict__ x,
                                                  const float* __restrict__ w,
                                                  const void* __restrict__ mask) {
    __shared__ float As[8][128];   // As[k][m] = W[m0+m, k0+k]
    __shared__ float Bs[8][128];   // Bs[k][n] = Xt[k0+k, n0+n] = x[b, n0+n, k0+k] (masked)
    const int b  = blockIdx.z;
    const int m0 = blockIdx.x * 128;
    const int n0 = blockIdx.y * 128;
    const int tid = threadIdx.x;
    const int u8 = g_mask_u8;

    const int row = tid >> 1;            // 0..127
    const int kh  = (tid & 1) * 4;       // 0 or 4
    const bool mk = mask_at(mask, b * Ln + n0 + row, u8);
    const float* wptr = w + (size_t)(m0 + row) * Dn + kh;
    const float* xptr = x + ((size_t)b * Ln + n0 + row) * Dn + kh;

    const int ty = tid >> 4, tx = tid & 15;
    float acc[8][8];
#pragma unroll
    for (int i = 0; i < 8; i++)
#pragma unroll
        for (int j = 0; j < 8; j++) acc[i][j] = 0.f;

    for (int k0 = 0; k0 < Dn; k0 += 8) {
        float4 wa = *(const float4*)(wptr + k0);
        float4 xa = mk ? make_float4(0.f, 0.f, 0.f, 0.f) : *(const float4*)(xptr + k0);
        As[kh + 0][row] = wa.x; As[kh + 1][row] = wa.y;
        As[kh + 2][row] = wa.z; As[kh + 3][row] = wa.w;
        Bs[kh + 0][row] = xa.x; Bs[kh + 1][row] = xa.y;
        Bs[kh + 2][row] = xa.z; Bs[kh + 3][row] = xa.w;
        __syncthreads();
#pragma unroll
        for (int kk = 0; kk < 8; kk++) {
            float4 a0 = *(float4*)&As[kk][ty * 8];
            float4 a1 = *(float4*)&As[kk][ty * 8 + 4];
            float4 b0 = *(float4*)&Bs[kk][tx * 8];
            float4 b1 = *(float4*)&Bs[kk][tx * 8 + 4];
            float av[8] = {a0.x, a0.y, a0.z, a0.w, a1.x, a1.y, a1.z, a1.w};
            float bv[8] = {b0.x, b0.y, b0.z, b0.w, b1.x, b1.y, b1.z, b1.w};
#pragma unroll
            for (int i = 0; i < 8; i++)
#pragma unroll
                for (int j = 0; j < 8; j++)
                    acc[i][j] = fmaf(av[i], bv[j], acc[i][j]);
        }
        __syncthreads();
    }

    const float s = (m0 < 1024) ? 0.125f : 1.0f;   // q rows scaled by d^-0.5
    float* outp = g_qkv + (size_t)b * O3 * Ln;
#pragma unroll
    for (int i = 0; i < 8; i++) {
        const int m = m0 + ty * 8 + i;
        float* p = outp + (size_t)m * Ln + n0 + tx * 8;
        float4 r0 = make_float4(acc[i][0] * s, acc[i][1] * s, acc[i][2] * s, acc[i][3] * s);
        float4 r1 = make_float4(acc[i][4] * s, acc[i][5] * s, acc[i][6] * s, acc[i][7] * s);
        *(float4*)p = r0;
        *(float4*)(p + 4) = r1;
    }
}

// -------- K2a: softmax over L on k rows (in place); also zero g_ctx --------
__global__ __launch_bounds__(256) void softmax_kernel(const void* __restrict__ mask) {
    const int b = blockIdx.y, r = blockIdx.x;
    const int tid = threadIdx.x;

    // zero the context accumulator (runs before context_kernel in stream order)
    {
        int gid = ((blockIdx.y * 1024 + blockIdx.x) << 8) + tid;
        if (gid < Bn * Hn * DHn * DHn) g_ctx[gid] = 0.f;
    }

    float* rowp = g_qkv + (size_t)b * O3 * Ln + (size_t)(1024 + r) * Ln;
    const int u8 = g_mask_u8;
    float vals[16];
    float sum = 0.f;
#pragma unroll
    for (int t = 0; t < 16; t++) {
        const int l = t * 256 + tid;
        const bool mk = mask_at(mask, b * Ln + l, u8);
        const float e = mk ? 0.f : expf(rowp[l]);
        vals[t] = e;
        sum += e;
    }
    __shared__ float red[256];
    red[tid] = sum;
    __syncthreads();
    for (int s = 128; s > 0; s >>= 1) {
        if (tid < s) red[tid] += red[tid + s];
        __syncthreads();
    }
    const float inv = 1.f / red[0];
#pragma unroll
    for (int t = 0; t < 16; t++) rowp[t * 256 + tid] = vals[t] * inv;
}

// -------- K2b: context[b,h] = Ksm(64xL) @ V^T(Lx64), split-K over L --------
#define CSPLIT 16
#define CCHUNK (Ln / CSPLIT)   // 256
__global__ __launch_bounds__(256) void context_kernel() {
    __shared__ float Kt[32][65];   // Kt[ll][d]
    __shared__ float Vt[32][68];   // Vt[ll][e]
    const int b = blockIdx.z, h = blockIdx.y, sp = blockIdx.x;
    const int tid = threadIdx.x;
    const int d  = tid >> 2;        // 0..63 (compute role)
    const int eg = tid & 3;
    const int ld = tid >> 2;        // 0..63 (loader row)
    const int lq = (tid & 3) * 8;   // loader l-offset

    const float* kbase = g_qkv + (size_t)b * O3 * Ln + (size_t)(1024 + h * 64) * Ln;
    const float* vbase = g_qkv + (size_t)b * O3 * Ln + (size_t)(2048 + h * 64) * Ln;
    const int l0 = sp * CCHUNK;

    float acc[16];
#pragma unroll
    for (int j = 0; j < 16; j++) acc[j] = 0.f;

    for (int ls = 0; ls < CCHUNK; ls += 32) {
        const float* kp = kbase + (size_t)ld * Ln + l0 + ls + lq;
        const float* vp = vbase + (size_t)ld * Ln + l0 + ls + lq;
        float4 k0v = *(const float4*)kp, k1v = *(const float4*)(kp + 4);
        float4 v0v = *(const float4*)vp, v1v = *(const float4*)(vp + 4);
        __syncthreads();
        Kt[lq + 0][ld] = k0v.x; Kt[lq + 1][ld] = k0v.y; Kt[lq + 2][ld] = k0v.z; Kt[lq + 3][ld] = k0v.w;
        Kt[lq + 4][ld] = k1v.x; Kt[lq + 5][ld] = k1v.y; Kt[lq + 6][ld] = k1v.z; Kt[lq + 7][ld] = k1v.w;
        Vt[lq + 0][ld] = v0v.x; Vt[lq + 1][ld] = v0v.y; Vt[lq + 2][ld] = v0v.z; Vt[lq + 3][ld] = v0v.w;
        Vt[lq + 4][ld] = v1v.x; Vt[lq + 5][ld] = v1v.y; Vt[lq + 6][ld] = v1v.z; Vt[lq + 7][ld] = v1v.w;
        __syncthreads();
#pragma unroll
        for (int ll = 0; ll < 32; ll++) {
            const float kd = Kt[ll][d];
            float4 va = *(float4*)&Vt[ll][eg * 16 + 0];
            float4 vb = *(float4*)&Vt[ll][eg * 16 + 4];
            float4 vc = *(float4*)&Vt[ll][eg * 16 + 8];
            float4 vd2 = *(float4*)&Vt[ll][eg * 16 + 12];
            acc[0]  = fmaf(kd, va.x, acc[0]);  acc[1]  = fmaf(kd, va.y, acc[1]);
            acc[2]  = fmaf(kd, va.z, acc[2]);  acc[3]  = fmaf(kd, va.w, acc[3]);
            acc[4]  = fmaf(kd, vb.x, acc[4]);  acc[5]  = fmaf(kd, vb.y, acc[5]);
            acc[6]  = fmaf(kd, vb.z, acc[6]);  acc[7]  = fmaf(kd, vb.w, acc[7]);
            acc[8]  = fmaf(kd, vc.x, acc[8]);  acc[9]  = fmaf(kd, vc.y, acc[9]);
            acc[10] = fmaf(kd, vc.z, acc[10]); acc[11] = fmaf(kd, vc.w, acc[11]);
            acc[12] = fmaf(kd, vd2.x, acc[12]); acc[13] = fmaf(kd, vd2.y, acc[13]);
            acc[14] = fmaf(kd, vd2.z, acc[14]); acc[15] = fmaf(kd, vd2.w, acc[15]);
        }
    }
    float* cptr = g_ctx + (((size_t)(b * Hn + h) * 64 + d) * 64) + eg * 16;
#pragma unroll
    for (int j = 0; j < 16; j++) atomicAdd(cptr + j, acc[j]);
}

// -------- K2c: Weff[b][:, h*64+e] = w_out[:, h*64+d] @ ctx[b,h,d,e] --------
__global__ __launch_bounds__(256) void weff_kernel(const float* __restrict__ wout) {
    __shared__ float Ws[64][65];   // Ws[d][oo]
    __shared__ float Cs[64][68];   // Cs[d][e]
    const int b = blockIdx.z, h = blockIdx.y, o0 = blockIdx.x * 64;
    const int tid = threadIdx.x;
    const int rr = tid >> 2;        // 0..63
    const int q4 = (tid & 3) * 16;

    const float* wp = wout + (size_t)(o0 + rr) * Dn + h * 64 + q4;
#pragma unroll
    for (int j = 0; j < 16; j += 4) {
        float4 t4 = *(const float4*)(wp + j);
        Ws[q4 + j + 0][rr] = t4.x; Ws[q4 + j + 1][rr] = t4.y;
        Ws[q4 + j + 2][rr] = t4.z; Ws[q4 + j + 3][rr] = t4.w;
    }
    const float* cp = g_ctx + ((size_t)(b * Hn + h) * 64 + rr) * 64 + q4;
#pragma unroll
    for (int j = 0; j < 16; j += 4) {
        float4 c4 = *(const float4*)(cp + j);
        *(float4*)&Cs[rr][q4 + j] = c4;
    }
    __syncthreads();

    const int oo = tid >> 2, eg = tid & 3;
    float acc[16];
#pragma unroll
    for (int j = 0; j < 16; j++) acc[j] = 0.f;
#pragma unroll 8
    for (int dd = 0; dd < 64; dd++) {
        const float wv = Ws[dd][oo];
        float4 c0 = *(float4*)&Cs[dd][eg * 16 + 0];
        float4 c1 = *(float4*)&Cs[dd][eg * 16 + 4];
        float4 c2 = *(float4*)&Cs[dd][eg * 16 + 8];
        float4 c3 = *(float4*)&Cs[dd][eg * 16 + 12];
        acc[0]  = fmaf(wv, c0.x, acc[0]);  acc[1]  = fmaf(wv, c0.y, acc[1]);
        acc[2]  = fmaf(wv, c0.z, acc[2]);  acc[3]  = fmaf(wv, c0.w, acc[3]);
        acc[4]  = fmaf(wv, c1.x, acc[4]);  acc[5]  = fmaf(wv, c1.y, acc[5]);
        acc[6]  = fmaf(wv, c1.z, acc[6]);  acc[7]  = fmaf(wv, c1.w, acc[7]);
        acc[8]  = fmaf(wv, c2.x, acc[8]);  acc[9]  = fmaf(wv, c2.y, acc[9]);
        acc[10] = fmaf(wv, c2.z, acc[10]); acc[11] = fmaf(wv, c2.w, acc[11]);
        acc[12] = fmaf(wv, c3.x, acc[12]); acc[13] = fmaf(wv, c3.y, acc[13]);
        acc[14] = fmaf(wv, c3.z, acc[14]); acc[15] = fmaf(wv, c3.w, acc[15]);
    }
    float* op = g_weff + (size_t)b * Dn * Dn + (size_t)(o0 + oo) * Dn + h * 64 + eg * 16;
#pragma unroll
    for (int j = 0; j < 16; j += 4) {
        float4 r = make_float4(acc[j], acc[j + 1], acc[j + 2], acc[j + 3]);
        *(float4*)(op + j) = r;
    }
}

// -------- K3: out[b,l,:] = Weff[b] @ q[b,:,l] + b_out --------
__global__ __launch_bounds__(256) void out_kernel(const float* __restrict__ bout,
                                                  float* __restrict__ out) {
    __shared__ float As[8][128];   // As[k][l] = q[b, c0+k, l0+l]
    __shared__ float Bs[8][128];   // Bs[k][o] = Weff[b, o0+o, c0+k]
    const int b  = blockIdx.z;
    const int l0 = blockIdx.x * 128;
    const int o0 = blockIdx.y * 128;
    const int tid = threadIdx.x;

    const float* q  = g_qkv + (size_t)b * O3 * Ln;     // q rows 0..1023
    const float* wf = g_weff + (size_t)b * Dn * Dn;

    const int akk = tid >> 5, alq = (tid & 31) * 4;
    const int boo = tid >> 1, bkh = (tid & 1) * 4;
    const int ty = tid >> 4, tx = tid & 15;

    float acc[8][8];
#pragma unroll
    for (int i = 0; i < 8; i++)
#pragma unroll
        for (int j = 0; j < 8; j++) acc[i][j] = 0.f;

    for (int c0 = 0; c0 < Dn; c0 += 8) {
        float4 a4 = *(const float4*)(q + (size_t)(c0 + akk) * Ln + l0 + alq);
        float4 b4 = *(const float4*)(wf + (size_t)(o0 + boo) * Dn + c0 + bkh);
        *(float4*)&As[akk][alq] = a4;
        Bs[bkh + 0][boo] = b4.x; Bs[bkh + 1][boo] = b4.y;
        Bs[bkh + 2][boo] = b4.z; Bs[bkh + 3][boo] = b4.w;
        __syncthreads();
#pragma unroll
        for (int kk = 0; kk < 8; kk++) {
            float4 a0 = *(float4*)&As[kk][ty * 8];
            float4 a1 = *(float4*)&As[kk][ty * 8 + 4];
            float4 b0 = *(float4*)&Bs[kk][tx * 8];
            float4 b1 = *(float4*)&Bs[kk][tx * 8 + 4];
            float av[8] = {a0.x, a0.y, a0.z, a0.w, a1.x, a1.y, a1.z, a1.w};
            float bv[8] = {b0.x, b0.y, b0.z, b0.w, b1.x, b1.y, b1.z, b1.w};
#pragma unroll
            for (int i = 0; i < 8; i++)
#pragma unroll
                for (int j = 0; j < 8; j++)
                    acc[i][j] = fmaf(av[i], bv[j], acc[i][j]);
        }
        __syncthreads();
    }

    float4 bb0 = *(const float4*)(bout + o0 + tx * 8);
    float4 bb1 = *(const float4*)(bout + o0 + tx * 8 + 4);
    const float bo[8] = {bb0.x, bb0.y, bb0.z, bb0.w, bb1.x, bb1.y, bb1.z, bb1.w};
#pragma unroll
    for (int i = 0; i < 8; i++) {
        const int l = l0 + ty * 8 + i;
        float* op = out + ((size_t)b * Ln + l) * Dn + o0 + tx * 8;
        float4 r0 = make_float4(acc[i][0] + bo[0], acc[i][1] + bo[1],
                                acc[i][2] + bo[2], acc[i][3] + bo[3]);
        float4 r1 = make_float4(acc[i][4] + bo[4], acc[i][5] + bo[5],
                                acc[i][6] + bo[6], acc[i][7] + bo[7]);
        *(float4*)op = r0;
        *(float4*)(op + 4) = r1;
    }
}

extern "C" void kernel_launch(void* const* d_in, const int* in_sizes, int n_in,
                              void* d_out, int out_size) {
    const float* x     = (const float*)d_in[0];
    const void*  masks = d_in[1];
    const float* w_qkv = (const float*)d_in[2];
    const float* w_out = (const float*)d_in[3];
    const float* b_out = (const float*)d_in[4];
    float* out = (float*)d_out;

    detect_mask_kernel<<<1, 256>>>((const unsigned char*)masks);
    qkv_kernel<<<dim3(24, 32, Bn), 256>>>(x, w_qkv, masks);
    softmax_kernel<<<dim3(1024, Bn), 256>>>(masks);      // also zeroes g_ctx
    context_kernel<<<dim3(CSPLIT, Hn, Bn), 256>>>();
    weff_kernel<<<dim3(16, Hn, Bn), 256>>>(w_out);
    out_kernel<<<dim3(32, 8, Bn), 256>>>(b_out, out);
}

// round 3
// speedup vs baseline: 2.2197x; 2.2197x over previous
#include <cuda_runtime.h>
#include <math.h>
#include <cstdint>

#define Bn 8
#define Ln 4096
#define Dn 1024
#define Hn 16
#define O3 3072

// ---------------- scratch (static device globals; no allocation) ----------------
__device__ __align__(256) float g_qkv[(size_t)Bn * O3 * Ln];   // 402 MB (B,3072,L)
__device__ __align__(256) float g_qT[(size_t)Bn * Ln * Dn];    // 134 MB (B,L,1024)
__device__ __align__(256) float g_ctx[Bn * Hn * 64 * 64];      // 2 MB
__device__ __align__(256) float g_weff[(size_t)Bn * Dn * Dn];  // 33 MB (b,o,c)
__device__ int g_mask_u8;

// ---------------- helpers ----------------
__device__ __forceinline__ uint32_t smem_u32(const void* p) {
    uint32_t a;
    asm("{ .reg .u64 t; cvta.to.shared.u64 t, %1; cvt.u32.u64 %0, t; }" : "=r"(a) : "l"(p));
    return a;
}
__device__ __forceinline__ uint32_t tf32c(float v) {
    uint32_t o;
    asm("cvt.rna.tf32.f32 %0, %1;" : "=r"(o) : "f"(v));
    return o;
}
__device__ __forceinline__ void cpasync16(uint32_t dst, const void* src) {
    asm volatile("cp.async.cg.shared.global [%0], [%1], 16;" :: "r"(dst), "l"(src) : "memory");
}
#define CP_COMMIT() asm volatile("cp.async.commit_group;" ::: "memory")
#define CP_WAIT1()  asm volatile("cp.async.wait_group 1;" ::: "memory")

__device__ __forceinline__ void mma8(float* c, uint32_t a0, uint32_t a1, uint32_t a2, uint32_t a3,
                                     uint32_t b0, uint32_t b1) {
    asm volatile("mma.sync.aligned.m16n8k8.row.col.f32.tf32.tf32.f32 "
        "{%0,%1,%2,%3}, {%4,%5,%6,%7}, {%8,%9}, {%0,%1,%2,%3};"
        : "+f"(c[0]), "+f"(c[1]), "+f"(c[2]), "+f"(c[3])
        : "r"(a0), "r"(a1), "r"(a2), "r"(a3), "r"(b0), "r"(b1));
}

__device__ __forceinline__ bool mask_at(const void* m, int idx, int u8) {
    if (u8) return ((const unsigned char*)m)[idx] != 0;
    return ((const int*)m)[idx] != 0;
}

// ---------------- big GEMM: C(M x N) = A(M x K) @ B(N x K)^T, tiles 128x256x32 ----------------
// MODE 0: B masked per n (GEMM1: qkv).  MODE 1: bias added per n (GEMM2: out).
#define PAD 36
#define STGF ((128 + 256) * PAD)   // floats per stage
#define NST 3
#define SMG (NST * STGF * 4)       // 165888 B

template <int MODE>
__global__ __launch_bounds__(256, 1) void gemm_tc(
    const float* __restrict__ Aall, const float* __restrict__ Ball,
    float* __restrict__ Call, const float* __restrict__ bias,
    const void* __restrict__ mask,
    int K, int ldc, size_t bsA, size_t bsB, size_t bsC) {
    extern __shared__ float sm[];
    const uint32_t smb = smem_u32(sm);
    const int tid = threadIdx.x, lane = tid & 31, wid = tid >> 5;
    const int b = blockIdx.z;
    const int m0 = blockIdx.x * 128, n0 = blockIdx.y * 256;
    const float* A = Aall + bsA * b;
    const float* Bp = Ball + bsB * b;
    float* C = Call + bsC * b;

    const int g = lane >> 2, t4 = lane & 3;
    const int warpM = wid & 1, warpN = wid >> 1;      // 2 x 4 warps
    const int mrow0 = warpM * 64, ncol0 = warpN * 64;

    float bmask[8];
    if (MODE == 0) {
        const int u8 = g_mask_u8;
#pragma unroll
        for (int nf = 0; nf < 8; nf++) {
            const int n = n0 + ncol0 + nf * 8 + g;
            bmask[nf] = mask_at(mask, b * Ln + n, u8) ? 0.f : 1.f;
        }
    }

    float acc[4][8][4];
#pragma unroll
    for (int mf = 0; mf < 4; mf++)
#pragma unroll
        for (int nf = 0; nf < 8; nf++)
#pragma unroll
            for (int j = 0; j < 4; j++) acc[mf][nf][j] = 0.f;

    auto load_stage = [&](int s, int ko) {
        const uint32_t sb = smb + (uint32_t)(s * STGF) * 4;
        {   // A: 128 rows x 32 cols, 2 threads per row
            const int row = tid >> 1, kh = (tid & 1) * 16;
            const float* src = A + (size_t)(m0 + row) * K + ko + kh;
            const uint32_t dst = sb + (uint32_t)(row * PAD + kh) * 4;
#pragma unroll
            for (int j = 0; j < 4; j++) cpasync16(dst + j * 16, src + j * 4);
        }
        {   // B: 256 rows x 32 cols, 1 thread per row
            const int row = tid;
            const float* src = Bp + (size_t)(n0 + row) * K + ko;
            const uint32_t dst = sb + (uint32_t)(128 * PAD + row * PAD) * 4;
#pragma unroll
            for (int j = 0; j < 8; j++) cpasync16(dst + j * 16, src + j * 4);
        }
    };

    const int NIT = K >> 5;
    load_stage(0, 0);  CP_COMMIT();
    load_stage(1, 32); CP_COMMIT();

    for (int i = 0; i < NIT; i++) {
        CP_WAIT1();
        __syncthreads();
        if (i + 2 < NIT) load_stage((i + 2) % NST, (i + 2) * 32);
        CP_COMMIT();

        const float* As = sm + (i % NST) * STGF;
        const float* Bs = As + 128 * PAD;
#pragma unroll
        for (int kk = 0; kk < 32; kk += 8) {
            uint32_t af[4][4];
#pragma unroll
            for (int mf = 0; mf < 4; mf++) {
                const float* ap = As + (mrow0 + mf * 16 + g) * PAD + kk + t4;
                af[mf][0] = tf32c(ap[0]);
                af[mf][1] = tf32c(ap[8 * PAD]);
                af[mf][2] = tf32c(ap[4]);
                af[mf][3] = tf32c(ap[8 * PAD + 4]);
            }
#pragma unroll
            for (int nf = 0; nf < 8; nf++) {
                const float* bp = Bs + (ncol0 + nf * 8 + g) * PAD + kk + t4;
                float b0v = bp[0], b1v = bp[4];
                if (MODE == 0) { b0v *= bmask[nf]; b1v *= bmask[nf]; }
                const uint32_t b0 = tf32c(b0v), b1 = tf32c(b1v);
#pragma unroll
                for (int mf = 0; mf < 4; mf++)
                    mma8(acc[mf][nf], af[mf][0], af[mf][1], af[mf][2], af[mf][3], b0, b1);
            }
        }
    }

#pragma unroll
    for (int mf = 0; mf < 4; mf++) {
        const int r0 = m0 + mrow0 + mf * 16 + g;
#pragma unroll
        for (int nf = 0; nf < 8; nf++) {
            const int c0 = n0 + ncol0 + nf * 8 + 2 * t4;
            float2 v0 = make_float2(acc[mf][nf][0], acc[mf][nf][1]);
            float2 v1 = make_float2(acc[mf][nf][2], acc[mf][nf][3]);
            if (MODE == 1) {
                const float2 bb = *(const float2*)(bias + c0);
                v0.x += bb.x; v0.y += bb.y; v1.x += bb.x; v1.y += bb.y;
            }
            *(float2*)(C + (size_t)r0 * ldc + c0) = v0;
            *(float2*)(C + (size_t)(r0 + 8) * ldc + c0) = v1;
        }
    }
}

// ---------------- context: per (b, head-pair): C(128x128) over K=L; keep diag 64x64 blocks ----------------
#define CSTGF (2 * 128 * PAD)
#define SMC (NST * CSTGF * 4)   // 110592 B

__global__ __launch_bounds__(256, 1) void ctx_tc() {
    extern __shared__ float sm[];
    const uint32_t smb = smem_u32(sm);
    const int tid = threadIdx.x, lane = tid & 31, wid = tid >> 5;
    const int b = blockIdx.z, hp = blockIdx.x;
    const float* A = g_qkv + (size_t)b * O3 * Ln + (size_t)(1024 + hp * 128) * Ln;   // ksm rows
    const float* Bp = g_qkv + (size_t)b * O3 * Ln + (size_t)(2048 + hp * 128) * Ln;  // v rows

    const int g = lane >> 2, t4 = lane & 3;
    const int warpM = wid & 1, warpN = wid >> 1;
    const int mrow0 = warpM * 64, ncol0 = warpN * 32;  // 2 x 4 warps, warp tile 64x32

    float acc[4][4][4];
#pragma unroll
    for (int mf = 0; mf < 4; mf++)
#pragma unroll
        for (int nf = 0; nf < 4; nf++)
#pragma unroll
            for (int j = 0; j < 4; j++) acc[mf][nf][j] = 0.f;

    auto load_stage = [&](int s, int ko) {
        const uint32_t sb = smb + (uint32_t)(s * CSTGF) * 4;
        const int row = tid >> 1, kh = (tid & 1) * 16;
        const float* srcA = A + (size_t)row * Ln + ko + kh;
        const float* srcB = Bp + (size_t)row * Ln + ko + kh;
        const uint32_t dA = sb + (uint32_t)(row * PAD + kh) * 4;
        const uint32_t dB = sb + (uint32_t)(128 * PAD + row * PAD + kh) * 4;
#pragma unroll
        for (int j = 0; j < 4; j++) {
            cpasync16(dA + j * 16, srcA + j * 4);
            cpasync16(dB + j * 16, srcB + j * 4);
        }
    };

    const int NIT = Ln >> 5;   // 128
    load_stage(0, 0);  CP_COMMIT();
    load_stage(1, 32); CP_COMMIT();

    for (int i = 0; i < NIT; i++) {
        CP_WAIT1();
        __syncthreads();
        if (i + 2 < NIT) load_stage((i + 2) % NST, (i + 2) * 32);
        CP_COMMIT();

        const float* As = sm + (i % NST) * CSTGF;
        const float* Bs = As + 128 * PAD;
#pragma unroll
        for (int kk = 0; kk < 32; kk += 8) {
            uint32_t af[4][4];
#pragma unroll
            for (int mf = 0; mf < 4; mf++) {
                const float* ap = As + (mrow0 + mf * 16 + g) * PAD + kk + t4;
                af[mf][0] = tf32c(ap[0]);
                af[mf][1] = tf32c(ap[8 * PAD]);
                af[mf][2] = tf32c(ap[4]);
                af[mf][3] = tf32c(ap[8 * PAD + 4]);
            }
#pragma unroll
            for (int nf = 0; nf < 4; nf++) {
                const float* bp = Bs + (ncol0 + nf * 8 + g) * PAD + kk + t4;
                const uint32_t b0 = tf32c(bp[0]), b1 = tf32c(bp[4]);
#pragma unroll
                for (int mf = 0; mf < 4; mf++)
                    mma8(acc[mf][nf], af[mf][0], af[mf][1], af[mf][2], af[mf][3], b0, b1);
            }
        }
    }

    // keep only diagonal head blocks: rows [warpM*64, +64) x cols [warpM*64, +64)
    if (warpM == (warpN >> 1)) {
        const int h = hp * 2 + warpM;
        float* cp = g_ctx + (size_t)(b * Hn + h) * 64 * 64;
#pragma unroll
        for (int mf = 0; mf < 4; mf++) {
            const int d0 = mf * 16 + g;
#pragma unroll
            for (int nf = 0; nf < 4; nf++) {
                const int e0 = (warpN & 1) * 32 + nf * 8 + 2 * t4;
                *(float2*)(cp + (size_t)d0 * 64 + e0) = make_float2(acc[mf][nf][0], acc[mf][nf][1]);
                *(float2*)(cp + (size_t)(d0 + 8) * 64 + e0) = make_float2(acc[mf][nf][2], acc[mf][nf][3]);
            }
        }
    }
}

// ---------------- mask detect ----------------
__global__ void detect_mask_kernel(const unsigned char* __restrict__ m) {
    __shared__ int found;
    if (threadIdx.x == 0) found = 0;
    __syncthreads();
    int local = 0;
    for (int i = threadIdx.x; i < 4096; i += blockDim.x)
        if ((i & 3) && m[i]) local = 1;
    if (local) atomicOr(&found, 1);
    __syncthreads();
    if (threadIdx.x == 0) g_mask_u8 = found;
}

// ---------------- softmax over L on k rows (masked), in place ----------------
__global__ __launch_bounds__(256) void softmax_kernel(const void* __restrict__ mask) {
    const int b = blockIdx.y, r = blockIdx.x;
    const int tid = threadIdx.x;
    float* rowp = g_qkv + (size_t)b * O3 * Ln + (size_t)(1024 + r) * Ln;
    const int u8 = g_mask_u8;
    float vals[16];
    float sum = 0.f;
#pragma unroll
    for (int t = 0; t < 16; t++) {
        const int l = t * 256 + tid;
        const bool mk = mask_at(mask, b * Ln + l, u8);
        const float e = mk ? 0.f : expf(rowp[l]);
        vals[t] = e;
        sum += e;
    }
    __shared__ float red[256];
    red[tid] = sum;
    __syncthreads();
    for (int s = 128; s > 0; s >>= 1) {
        if (tid < s) red[tid] += red[tid + s];
        __syncthreads();
    }
    const float inv = 1.f / red[0];
#pragma unroll
    for (int t = 0; t < 16; t++) rowp[t * 256 + tid] = vals[t] * inv;
}

// ---------------- weff[b][o][h*64+e] = sum_d w_out[o][h*64+d] * ctx[b,h,d,e] ----------------
__global__ __launch_bounds__(256) void weff_kernel(const float* __restrict__ wout) {
    __shared__ float Ws[64][65];
    __shared__ float Cs[64][68];
    const int b = blockIdx.z, h = blockIdx.y, o0 = blockIdx.x * 64;
    const int tid = threadIdx.x;
    const int rr = tid >> 2;
    const int q4 = (tid & 3) * 16;
    const float* wp = wout + (size_t)(o0 + rr) * Dn + h * 64 + q4;
#pragma unroll
    for (int j = 0; j < 16; j += 4) {
        float4 t4v = *(const float4*)(wp + j);
        Ws[q4 + j + 0][rr] = t4v.x; Ws[q4 + j + 1][rr] = t4v.y;
        Ws[q4 + j + 2][rr] = t4v.z; Ws[q4 + j + 3][rr] = t4v.w;
    }
    const float* cp = g_ctx + ((size_t)(b * Hn + h) * 64 + rr) * 64 + q4;
#pragma unroll
    for (int j = 0; j < 16; j += 4) *(float4*)&Cs[rr][q4 + j] = *(const float4*)(cp + j);
    __syncthreads();

    const int oo = tid >> 2, eg = tid & 3;
    float acc[16];
#pragma unroll
    for (int j = 0; j < 16; j++) acc[j] = 0.f;
#pragma unroll 8
    for (int dd = 0; dd < 64; dd++) {
        const float wv = Ws[dd][oo];
#pragma unroll
        for (int j = 0; j < 16; j++) acc[j] = fmaf(wv, Cs[dd][eg * 16 + j], acc[j]);
    }
    float* op = g_weff + (size_t)b * Dn * Dn + (size_t)(o0 + oo) * Dn + h * 64 + eg * 16;
#pragma unroll
    for (int j = 0; j < 16; j += 4)
        *(float4*)(op + j) = make_float4(acc[j], acc[j + 1], acc[j + 2], acc[j + 3]);
}

// ---------------- transpose q -> qT with 0.125 scale ----------------
__global__ __launch_bounds__(256) void transpose_q() {
    __shared__ float t[32][33];
    const int b = blockIdx.z, l0 = blockIdx.x * 32, c0 = blockIdx.y * 32;
    const int tx = threadIdx.x & 31, ty = threadIdx.x >> 5;
    const float* q = g_qkv + (size_t)b * O3 * Ln;
#pragma unroll
    for (int k = 0; k < 4; k++)
        t[ty + 8 * k][tx] = q[(size_t)(c0 + ty + 8 * k) * Ln + l0 + tx];
    __syncthreads();
#pragma unroll
    for (int k = 0; k < 4; k++) {
        const int l = l0 + ty + 8 * k;
        g_qT[((size_t)b * Ln + l) * Dn + c0 + tx] = 0.125f * t[tx][ty + 8 * k];
    }
}

// ---------------- host side ----------------
extern "C" void kernel_launch(void* const* d_in, const int* in_sizes, int n_in,
                              void* d_out, int out_size) {
    const float* x = (const float*)d_in[0];
    const void* masks = d_in[1];
    const float* w_qkv = (const float*)d_in[2];
    const float* w_out = (const float*)d_in[3];
    const float* b_out = (const float*)d_in[4];
    float* out = (float*)d_out;

    void *pQ, *pQT, *pWE;
    cudaGetSymbolAddress(&pQ, g_qkv);
    cudaGetSymbolAddress(&pQT, g_qT);
    cudaGetSymbolAddress(&pWE, g_weff);

    cudaFuncSetAttribute(gemm_tc<0>, cudaFuncAttributeMaxDynamicSharedMemorySize, SMG);
    cudaFuncSetAttribute(gemm_tc<1>, cudaFuncAttributeMaxDynamicSharedMemorySize, SMG);
    cudaFuncSetAttribute(ctx_tc, cudaFuncAttributeMaxDynamicSharedMemorySize, SMC);

    detect_mask_kernel<<<1, 256>>>((const unsigned char*)masks);

    // GEMM1: g_qkv[b](3072 x 4096) = w_qkv(3072 x 1024) @ x[b](4096 x 1024)^T, masked n
    gemm_tc<0><<<dim3(24, 16, Bn), 256, SMG>>>(
        w_qkv, x, (float*)pQ, nullptr, masks,
        Dn, Ln, (size_t)0, (size_t)Ln * Dn, (size_t)O3 * Ln);

    softmax_kernel<<<dim3(1024, Bn), 256>>>(masks);

    ctx_tc<<<dim3(8, 1, Bn), 256, SMC>>>();

    weff_kernel<<<dim3(16, Hn, Bn), 256>>>(w_out);

    transpose_q<<<dim3(128, 32, Bn), 256>>>();

    // GEMM2: out[b](4096 x 1024) = g_qT[b](4096 x 1024) @ g_weff[b](1024 x 1024)^T + b_out
    gemm_tc<1><<<dim3(32, 4, Bn), 256, SMG>>>(
        (const float*)pQT, (const float*)pWE, out, b_out, nullptr,
        Dn, Dn, (size_t)Ln * Dn, (size_t)Dn * Dn, (size_t)Ln * Dn);
}

// round 4
// speedup vs baseline: 2.4379x; 1.0983x over previous
#include <cuda_runtime.h>
#include <math.h>
#include <cstdint>

#define Bn 8
#define Ln 4096
#define Dn 1024
#define Hn 16
#define O3 3072

// ---------------- scratch (static device globals; no allocation) ----------------
__device__ __align__(256) float g_qkv[(size_t)Bn * O3 * Ln];   // 402 MB (B,3072,L) tf32
__device__ __align__(256) float g_qT[(size_t)Bn * Ln * Dn];    // 134 MB (B,L,1024) tf32
__device__ __align__(256) float g_x32[(size_t)Bn * Ln * Dn];   // 134 MB masked+rounded x
__device__ __align__(256) float g_w32[(size_t)O3 * Dn];        // 12 MB  rounded w_qkv
__device__ __align__(256) float g_ctx[Bn * Hn * 64 * 64];      // 2 MB
__device__ __align__(256) float g_weff[(size_t)Bn * Dn * Dn];  // 33 MB (b,o,c) tf32
__device__ int g_mask_u8;

// ---------------- helpers ----------------
__device__ __forceinline__ uint32_t smem_u32(const void* p) {
    uint32_t a;
    asm("{ .reg .u64 t; cvta.to.shared.u64 t, %1; cvt.u32.u64 %0, t; }" : "=r"(a) : "l"(p));
    return a;
}
__device__ __forceinline__ float tf32r(float v) {
    uint32_t o;
    asm("cvt.rna.tf32.f32 %0, %1;" : "=r"(o) : "f"(v));
    return __uint_as_float(o);
}
__device__ __forceinline__ void cpasync16(uint32_t dst, const void* src) {
    asm volatile("cp.async.cg.shared.global [%0], [%1], 16;" :: "r"(dst), "l"(src) : "memory");
}
#define CP_COMMIT() asm volatile("cp.async.commit_group;" ::: "memory")
#define CP_WAIT1()  asm volatile("cp.async.wait_group 1;" ::: "memory")

__device__ __forceinline__ void mma8(float* c, uint32_t a0, uint32_t a1, uint32_t a2, uint32_t a3,
                                     uint32_t b0, uint32_t b1) {
    asm volatile("mma.sync.aligned.m16n8k8.row.col.f32.tf32.tf32.f32 "
        "{%0,%1,%2,%3}, {%4,%5,%6,%7}, {%8,%9}, {%0,%1,%2,%3};"
        : "+f"(c[0]), "+f"(c[1]), "+f"(c[2]), "+f"(c[3])
        : "r"(a0), "r"(a1), "r"(a2), "r"(a3), "r"(b0), "r"(b1));
}

__device__ __forceinline__ bool mask_at(const void* m, int idx, int u8) {
    if (u8) return ((const unsigned char*)m)[idx] != 0;
    return ((const int*)m)[idx] != 0;
}
__device__ __forceinline__ uint32_t ldr(const float* p) { return __float_as_uint(*p); }

// ---------------- big GEMM: C(M x N) = A(M x K) @ B(N x K)^T, tiles 128x256x32 ----------------
// MODE 0: round output to tf32 (GEMM1).  MODE 1: add bias (GEMM2, final output).
#define PAD 36
#define STGF ((128 + 256) * PAD)
#define NST 3
#define SMG (NST * STGF * 4)   // 165888 B

template <int MODE>
__global__ __launch_bounds__(256, 1) void gemm_tc(
    const float* __restrict__ Aall, const float* __restrict__ Ball,
    float* __restrict__ Call, const float* __restrict__ bias,
    int K, int ldc, size_t bsA, size_t bsB, size_t bsC) {
    extern __shared__ float sm[];
    const uint32_t smb = smem_u32(sm);
    const int tid = threadIdx.x, lane = tid & 31, wid = tid >> 5;
    const int b = blockIdx.z;
    const int m0 = blockIdx.x * 128, n0 = blockIdx.y * 256;
    const float* A = Aall + bsA * b;
    const float* Bp = Ball + bsB * b;
    float* C = Call + bsC * b;

    const int g = lane >> 2, t4 = lane & 3;
    const int warpM = wid & 1, warpN = wid >> 1;      // 2 x 4 warps
    const int mrow0 = warpM * 64, ncol0 = warpN * 64;

    float acc[4][8][4];
#pragma unroll
    for (int mf = 0; mf < 4; mf++)
#pragma unroll
        for (int nf = 0; nf < 8; nf++)
#pragma unroll
            for (int j = 0; j < 4; j++) acc[mf][nf][j] = 0.f;

    auto load_stage = [&](int s, int ko) {
        const uint32_t sb = smb + (uint32_t)(s * STGF) * 4;
        {   // A: 128 rows x 32 cols
            const int row = tid >> 1, kh = (tid & 1) * 16;
            const float* src = A + (size_t)(m0 + row) * K + ko + kh;
            const uint32_t dst = sb + (uint32_t)(row * PAD + kh) * 4;
#pragma unroll
            for (int j = 0; j < 4; j++) cpasync16(dst + j * 16, src + j * 4);
        }
        {   // B: 256 rows x 32 cols
            const int row = tid;
            const float* src = Bp + (size_t)(n0 + row) * K + ko;
            const uint32_t dst = sb + (uint32_t)(128 * PAD + row * PAD) * 4;
#pragma unroll
            for (int j = 0; j < 8; j++) cpasync16(dst + j * 16, src + j * 4);
        }
    };

    const int NIT = K >> 5;
    load_stage(0, 0);  CP_COMMIT();
    load_stage(1, 32); CP_COMMIT();

    for (int i = 0; i < NIT; i++) {
        CP_WAIT1();
        __syncthreads();
        if (i + 2 < NIT) load_stage((i + 2) % NST, (i + 2) * 32);
        CP_COMMIT();

        const float* As = sm + (i % NST) * STGF;
        const float* Bs = As + 128 * PAD;
#pragma unroll
        for (int kk = 0; kk < 32; kk += 8) {
            uint32_t af[4][4];
#pragma unroll
            for (int mf = 0; mf < 4; mf++) {
                const float* ap = As + (mrow0 + mf * 16 + g) * PAD + kk + t4;
                af[mf][0] = ldr(ap);
                af[mf][1] = ldr(ap + 8 * PAD);
                af[mf][2] = ldr(ap + 4);
                af[mf][3] = ldr(ap + 8 * PAD + 4);
            }
#pragma unroll
            for (int nf = 0; nf < 8; nf++) {
                const float* bp = Bs + (ncol0 + nf * 8 + g) * PAD + kk + t4;
                const uint32_t b0 = ldr(bp), b1 = ldr(bp + 4);
#pragma unroll
                for (int mf = 0; mf < 4; mf++)
                    mma8(acc[mf][nf], af[mf][0], af[mf][1], af[mf][2], af[mf][3], b0, b1);
            }
        }
    }

#pragma unroll
    for (int mf = 0; mf < 4; mf++) {
        const int r0 = m0 + mrow0 + mf * 16 + g;
#pragma unroll
        for (int nf = 0; nf < 8; nf++) {
            const int c0 = n0 + ncol0 + nf * 8 + 2 * t4;
            float2 v0 = make_float2(acc[mf][nf][0], acc[mf][nf][1]);
            float2 v1 = make_float2(acc[mf][nf][2], acc[mf][nf][3]);
            if (MODE == 1) {
                const float2 bb = *(const float2*)(bias + c0);
                v0.x += bb.x; v0.y += bb.y; v1.x += bb.x; v1.y += bb.y;
            } else {
                v0.x = tf32r(v0.x); v0.y = tf32r(v0.y);
                v1.x = tf32r(v1.x); v1.y = tf32r(v1.y);
            }
            *(float2*)(C + (size_t)r0 * ldc + c0) = v0;
            *(float2*)(C + (size_t)(r0 + 8) * ldc + c0) = v1;
        }
    }
}

// ---------------- context: split-K over L, diag 64x64 blocks via atomicAdd ----------------
#define CSPL 8
#define CCH (Ln / CSPL)         // 512
#define CSTGF (2 * 128 * PAD)
#define SMC (NST * CSTGF * 4)   // 110592 B

__global__ __launch_bounds__(256, 1) void ctx_tc() {
    extern __shared__ float sm[];
    const uint32_t smb = smem_u32(sm);
    const int tid = threadIdx.x, lane = tid & 31, wid = tid >> 5;
    const int b = blockIdx.z, hp = blockIdx.x, sp = blockIdx.y;
    const int l0 = sp * CCH;
    const float* A = g_qkv + (size_t)b * O3 * Ln + (size_t)(1024 + hp * 128) * Ln + l0;   // ksm
    const float* Bp = g_qkv + (size_t)b * O3 * Ln + (size_t)(2048 + hp * 128) * Ln + l0;  // v

    const int g = lane >> 2, t4 = lane & 3;
    const int warpM = wid & 1, warpN = wid >> 1;
    const int mrow0 = warpM * 64, ncol0 = warpN * 32;

    float acc[4][4][4];
#pragma unroll
    for (int mf = 0; mf < 4; mf++)
#pragma unroll
        for (int nf = 0; nf < 4; nf++)
#pragma unroll
            for (int j = 0; j < 4; j++) acc[mf][nf][j] = 0.f;

    auto load_stage = [&](int s, int ko) {
        const uint32_t sb = smb + (uint32_t)(s * CSTGF) * 4;
        const int row = tid >> 1, kh = (tid & 1) * 16;
        const float* srcA = A + (size_t)row * Ln + ko + kh;
        const float* srcB = Bp + (size_t)row * Ln + ko + kh;
        const uint32_t dA = sb + (uint32_t)(row * PAD + kh) * 4;
        const uint32_t dB = sb + (uint32_t)(128 * PAD + row * PAD + kh) * 4;
#pragma unroll
        for (int j = 0; j < 4; j++) {
            cpasync16(dA + j * 16, srcA + j * 4);
            cpasync16(dB + j * 16, srcB + j * 4);
        }
    };

    const int NIT = CCH >> 5;   // 16
    load_stage(0, 0);  CP_COMMIT();
    load_stage(1, 32); CP_COMMIT();

    for (int i = 0; i < NIT; i++) {
        CP_WAIT1();
        __syncthreads();
        if (i + 2 < NIT) load_stage((i + 2) % NST, (i + 2) * 32);
        CP_COMMIT();

        const float* As = sm + (i % NST) * CSTGF;
        const float* Bs = As + 128 * PAD;
#pragma unroll
        for (int kk = 0; kk < 32; kk += 8) {
            uint32_t af[4][4];
#pragma unroll
            for (int mf = 0; mf < 4; mf++) {
                const float* ap = As + (mrow0 + mf * 16 + g) * PAD + kk + t4;
                af[mf][0] = ldr(ap);
                af[mf][1] = ldr(ap + 8 * PAD);
                af[mf][2] = ldr(ap + 4);
                af[mf][3] = ldr(ap + 8 * PAD + 4);
            }
#pragma unroll
            for (int nf = 0; nf < 4; nf++) {
                const float* bp = Bs + (ncol0 + nf * 8 + g) * PAD + kk + t4;
                const uint32_t b0 = ldr(bp), b1 = ldr(bp + 4);
#pragma unroll
                for (int mf = 0; mf < 4; mf++)
                    mma8(acc[mf][nf], af[mf][0], af[mf][1], af[mf][2], af[mf][3], b0, b1);
            }
        }
    }

    if (warpM == (warpN >> 1)) {
        const int h = hp * 2 + warpM;
        float* cp = g_ctx + (size_t)(b * Hn + h) * 64 * 64;
#pragma unroll
        for (int mf = 0; mf < 4; mf++) {
            const int d0 = mf * 16 + g;
#pragma unroll
            for (int nf = 0; nf < 4; nf++) {
                const int e0 = (warpN & 1) * 32 + nf * 8 + 2 * t4;
                atomicAdd(cp + (size_t)d0 * 64 + e0, acc[mf][nf][0]);
                atomicAdd(cp + (size_t)d0 * 64 + e0 + 1, acc[mf][nf][1]);
                atomicAdd(cp + (size_t)(d0 + 8) * 64 + e0, acc[mf][nf][2]);
                atomicAdd(cp + (size_t)(d0 + 8) * 64 + e0 + 1, acc[mf][nf][3]);
            }
        }
    }
}

// ---------------- mask detect ----------------
__global__ void detect_mask_kernel(const unsigned char* __restrict__ m) {
    __shared__ int found;
    if (threadIdx.x == 0) found = 0;
    __syncthreads();
    int local = 0;
    for (int i = threadIdx.x; i < 4096; i += blockDim.x)
        if ((i & 3) && m[i]) local = 1;
    if (local) atomicOr(&found, 1);
    __syncthreads();
    if (threadIdx.x == 0) g_mask_u8 = found;
}

// ---------------- prep: rounded w_qkv; rounded + mask-zeroed x ----------------
__global__ __launch_bounds__(256) void prep_round(const float4* __restrict__ x,
                                                  const float4* __restrict__ w,
                                                  const void* __restrict__ mask) {
    const size_t NX = (size_t)Bn * Ln * Dn / 4;
    const size_t NW = (size_t)O3 * Dn / 4;
    size_t i = (size_t)blockIdx.x * blockDim.x + threadIdx.x;
    if (i < NX) {
        const size_t flat = i * 4;
        const int bl = (int)(flat >> 10);          // b*Ln + l
        const bool mk = mask_at(mask, bl, g_mask_u8);
        float4 v = mk ? make_float4(0.f, 0.f, 0.f, 0.f) : x[i];
        v.x = tf32r(v.x); v.y = tf32r(v.y); v.z = tf32r(v.z); v.w = tf32r(v.w);
        ((float4*)g_x32)[i] = v;
    } else if (i < NX + NW) {
        float4 v = w[i - NX];
        v.x = tf32r(v.x); v.y = tf32r(v.y); v.z = tf32r(v.z); v.w = tf32r(v.w);
        ((float4*)g_w32)[i - NX] = v;
    }
}

// ---------------- softmax on k rows (masked, tf32 out); zeroes g_ctx ----------------
__global__ __launch_bounds__(256) void softmax_kernel(const void* __restrict__ mask) {
    const int b = blockIdx.y, r = blockIdx.x;
    const int tid = threadIdx.x;
    {   // zero context accumulator (runs before ctx_tc in stream order)
        const int gid = ((blockIdx.y * 1024 + blockIdx.x) << 8) + tid;
        if (gid < Bn * Hn * 64 * 64) g_ctx[gid] = 0.f;
    }
    float* rowp = g_qkv + (size_t)b * O3 * Ln + (size_t)(1024 + r) * Ln;
    const int u8 = g_mask_u8;
    float vals[16];
    float sum = 0.f;
#pragma unroll
    for (int t = 0; t < 16; t++) {
        const int l = t * 256 + tid;
        const bool mk = mask_at(mask, b * Ln + l, u8);
        const float e = mk ? 0.f : expf(rowp[l]);
        vals[t] = e;
        sum += e;
    }
    __shared__ float red[256];
    red[tid] = sum;
    __syncthreads();
    for (int s = 128; s > 0; s >>= 1) {
        if (tid < s) red[tid] += red[tid + s];
        __syncthreads();
    }
    const float inv = 1.f / red[0];
#pragma unroll
    for (int t = 0; t < 16; t++) rowp[t * 256 + tid] = tf32r(vals[t] * inv);
}

// ---------------- weff (SIMT, f32 in, tf32 out) ----------------
__global__ __launch_bounds__(256) void weff_kernel(const float* __restrict__ wout) {
    __shared__ float Ws[64][65];
    __shared__ float Cs[64][68];
    const int b = blockIdx.z, h = blockIdx.y, o0 = blockIdx.x * 64;
    const int tid = threadIdx.x;
    const int rr = tid >> 2;
    const int q4 = (tid & 3) * 16;
    const float* wp = wout + (size_t)(o0 + rr) * Dn + h * 64 + q4;
#pragma unroll
    for (int j = 0; j < 16; j += 4) {
        float4 t4v = *(const float4*)(wp + j);
        Ws[q4 + j + 0][rr] = t4v.x; Ws[q4 + j + 1][rr] = t4v.y;
        Ws[q4 + j + 2][rr] = t4v.z; Ws[q4 + j + 3][rr] = t4v.w;
    }
    const float* cp = g_ctx + ((size_t)(b * Hn + h) * 64 + rr) * 64 + q4;
#pragma unroll
    for (int j = 0; j < 16; j += 4) *(float4*)&Cs[rr][q4 + j] = *(const float4*)(cp + j);
    __syncthreads();

    const int oo = tid >> 2, eg = tid & 3;
    float acc[16];
#pragma unroll
    for (int j = 0; j < 16; j++) acc[j] = 0.f;
#pragma unroll 8
    for (int dd = 0; dd < 64; dd++) {
        const float wv = Ws[dd][oo];
#pragma unroll
        for (int j = 0; j < 16; j++) acc[j] = fmaf(wv, Cs[dd][eg * 16 + j], acc[j]);
    }
    float* op = g_weff + (size_t)b * Dn * Dn + (size_t)(o0 + oo) * Dn + h * 64 + eg * 16;
#pragma unroll
    for (int j = 0; j < 16; j += 4)
        *(float4*)(op + j) = make_float4(tf32r(acc[j]), tf32r(acc[j + 1]),
                                         tf32r(acc[j + 2]), tf32r(acc[j + 3]));
}

// ---------------- transpose q -> qT with 0.125 scale (exact in tf32) ----------------
__global__ __launch_bounds__(256) void transpose_q() {
    __shared__ float t[32][33];
    const int b = blockIdx.z, l0 = blockIdx.x * 32, c0 = blockIdx.y * 32;
    const int tx = threadIdx.x & 31, ty = threadIdx.x >> 5;
    const float* q = g_qkv + (size_t)b * O3 * Ln;
#pragma unroll
    for (int k = 0; k < 4; k++)
        t[ty + 8 * k][tx] = q[(size_t)(c0 + ty + 8 * k) * Ln + l0 + tx];
    __syncthreads();
#pragma unroll
    for (int k = 0; k < 4; k++) {
        const int l = l0 + ty + 8 * k;
        g_qT[((size_t)b * Ln + l) * Dn + c0 + tx] = 0.125f * t[tx][ty + 8 * k];
    }
}

// ---------------- host side ----------------
extern "C" void kernel_launch(void* const* d_in, const int* in_sizes, int n_in,
                              void* d_out, int out_size) {
    const float* x = (const float*)d_in[0];
    const void* masks = d_in[1];
    const float* w_qkv = (const float*)d_in[2];
    const float* w_out = (const float*)d_in[3];
    const float* b_out = (const float*)d_in[4];
    float* out = (float*)d_out;

    void *pQ, *pQT, *pWE, *pX, *pW;
    cudaGetSymbolAddress(&pQ, g_qkv);
    cudaGetSymbolAddress(&pQT, g_qT);
    cudaGetSymbolAddress(&pWE, g_weff);
    cudaGetSymbolAddress(&pX, g_x32);
    cudaGetSymbolAddress(&pW, g_w32);

    cudaFuncSetAttribute(gemm_tc<0>, cudaFuncAttributeMaxDynamicSharedMemorySize, SMG);
    cudaFuncSetAttribute(gemm_tc<1>, cudaFuncAttributeMaxDynamicSharedMemorySize, SMG);
    cudaFuncSetAttribute(ctx_tc, cudaFuncAttributeMaxDynamicSharedMemorySize, SMC);

    detect_mask_kernel<<<1, 256>>>((const unsigned char*)masks);
    prep_round<<<35840, 256>>>((const float4*)x, (const float4*)w_qkv, masks);

    // GEMM1: g_qkv[b](3072 x 4096) = g_w32(3072 x 1024) @ g_x32[b](4096 x 1024)^T
    gemm_tc<0><<<dim3(24, 16, Bn), 256, SMG>>>(
        (const float*)pW, (const float*)pX, (float*)pQ, nullptr,
        Dn, Ln, (size_t)0, (size_t)Ln * Dn, (size_t)O3 * Ln);

    softmax_kernel<<<dim3(1024, Bn), 256>>>(masks);

    ctx_tc<<<dim3(8, CSPL, Bn), 256, SMC>>>();

    weff_kernel<<<dim3(16, Hn, Bn), 256>>>(w_out);

    transpose_q<<<dim3(128, 32, Bn), 256>>>();

    // GEMM2: out[b](4096 x 1024) = g_qT[b](4096 x 1024) @ g_weff[b](1024 x 1024)^T + b_out
    gemm_tc<1><<<dim3(32, 4, Bn), 256, SMG>>>(
        (const float*)pQT, (const float*)pWE, out, b_out,
        Dn, Dn, (size_t)Ln * Dn, (size_t)Dn * Dn, (size_t)Ln * Dn);
}

// round 6
// speedup vs baseline: 4.1501x; 1.7023x over previous
#include <cuda_runtime.h>
#include <math.h>
#include <cstdint>

#define Bn 8
#define Ln 4096
#define Dn 1024
#define Hn 16
#define O3 3072

// ---------------- scratch (static device globals; no allocation) ----------------
__device__ __align__(256) float g_qkv[(size_t)Bn * O3 * Ln];   // (B,3072,L) tf32, compact cols
__device__ __align__(256) float g_qT[(size_t)Bn * Ln * Dn];    // (B,Lc,1024) tf32
__device__ __align__(256) float g_x32[(size_t)Bn * Ln * Dn];   // compacted+rounded x
__device__ __align__(256) float g_outc[(size_t)Bn * Ln * Dn];  // compacted output
__device__ __align__(256) float g_w32[(size_t)O3 * Dn];        // rounded w_qkv
__device__ __align__(256) float g_ctx[Bn * Hn * 64 * 64];
__device__ __align__(256) float g_weff[(size_t)Bn * Dn * Dn];
__device__ int g_idx[Bn][Ln];    // compact j -> original l
__device__ int g_rank[Bn][Ln];   // original l -> compact j or -1
__device__ int g_Lc[Bn];         // unmasked count
__device__ int g_Lcp256[Bn];     // padded to 256
__device__ int g_Lcp128[Bn];     // padded to 128
__device__ int g_mask_u8;

// ---------------- helpers ----------------
__device__ __forceinline__ uint32_t smem_u32(const void* p) {
    uint32_t a;
    asm("{ .reg .u64 t; cvta.to.shared.u64 t, %1; cvt.u32.u64 %0, t; }" : "=r"(a) : "l"(p));
    return a;
}
__device__ __forceinline__ float tf32r(float v) {
    uint32_t o;
    asm("cvt.rna.tf32.f32 %0, %1;" : "=r"(o) : "f"(v));
    return __uint_as_float(o);
}
__device__ __forceinline__ void cpasync16(uint32_t dst, const void* src) {
    asm volatile("cp.async.cg.shared.global [%0], [%1], 16;" :: "r"(dst), "l"(src) : "memory");
}
#define CP_COMMIT() asm volatile("cp.async.commit_group;" ::: "memory")
#define CP_WAIT1()  asm volatile("cp.async.wait_group 1;" ::: "memory")

__device__ __forceinline__ void mma8(float* c, uint32_t a0, uint32_t a1, uint32_t a2, uint32_t a3,
                                     uint32_t b0, uint32_t b1) {
    asm volatile("mma.sync.aligned.m16n8k8.row.col.f32.tf32.tf32.f32 "
        "{%0,%1,%2,%3}, {%4,%5,%6,%7}, {%8,%9}, {%0,%1,%2,%3};"
        : "+f"(c[0]), "+f"(c[1]), "+f"(c[2]), "+f"(c[3])
        : "r"(a0), "r"(a1), "r"(a2), "r"(a3), "r"(b0), "r"(b1));
}
__device__ __forceinline__ bool mask_at(const void* m, int idx, int u8) {
    if (u8) return ((const unsigned char*)m)[idx] != 0;
    return ((const int*)m)[idx] != 0;
}
__device__ __forceinline__ uint32_t ldr(const float* p) { return __float_as_uint(*p); }

// ---------------- mask detect + compaction maps ----------------
__global__ void detect_mask_kernel(const unsigned char* __restrict__ m) {
    __shared__ int found;
    if (threadIdx.x == 0) found = 0;
    __syncthreads();
    int local = 0;
    for (int i = threadIdx.x; i < 4096; i += blockDim.x)
        if ((i & 3) && m[i]) local = 1;
    if (local) atomicOr(&found, 1);
    __syncthreads();
    if (threadIdx.x == 0) g_mask_u8 = found;
}

__global__ __launch_bounds__(256) void count_kernel(const void* __restrict__ mask) {
    const int b = blockIdx.x, tid = threadIdx.x;
    const int u8 = g_mask_u8;
    __shared__ int cnt[256];
    __shared__ int excl[257];
    int loc[16], c = 0;
#pragma unroll
    for (int t = 0; t < 16; t++) {
        const int l = tid * 16 + t;
        loc[t] = mask_at(mask, b * Ln + l, u8) ? 0 : 1;
        c += loc[t];
    }
    cnt[tid] = c;
    __syncthreads();
    if (tid == 0) {
        int s = 0;
        for (int i = 0; i < 256; i++) { excl[i] = s; s += cnt[i]; }
        excl[256] = s;
        g_Lc[b] = s;
        g_Lcp256[b] = (s + 255) & ~255;
        g_Lcp128[b] = (s + 127) & ~127;
    }
    __syncthreads();
    int j = excl[tid];
#pragma unroll
    for (int t = 0; t < 16; t++) {
        const int l = tid * 16 + t;
        if (loc[t]) { g_idx[b][j] = l; g_rank[b][l] = j; j++; }
        else g_rank[b][l] = -1;
    }
}

// ---------------- prep: rounded w; compacted+rounded x (zero pad) ----------------
__global__ __launch_bounds__(256) void prep_w(const float4* __restrict__ w) {
    const int r = blockIdx.x, tid = threadIdx.x;
    float4 v = w[(size_t)r * 256 + tid];
    v.x = tf32r(v.x); v.y = tf32r(v.y); v.z = tf32r(v.z); v.w = tf32r(v.w);
    ((float4*)g_w32)[(size_t)r * 256 + tid] = v;
}

__global__ __launch_bounds__(256) void prep_x(const float4* __restrict__ x) {
    const int b = blockIdx.y, j = blockIdx.x, tid = threadIdx.x;
    if (j >= g_Lcp256[b]) return;
    float4* dst = (float4*)g_x32 + ((size_t)b * Ln + j) * 256;
    if (j >= g_Lc[b]) { dst[tid] = make_float4(0.f, 0.f, 0.f, 0.f); return; }
    const int l = g_idx[b][j];
    float4 v = x[((size_t)b * Ln + l) * 256 + tid];
    v.x = tf32r(v.x); v.y = tf32r(v.y); v.z = tf32r(v.z); v.w = tf32r(v.w);
    dst[tid] = v;
}

// ---------------- big GEMM: C(M x N) = A(M x K) @ B(N x K)^T, tiles 128x256x32 ----------------
// MODE 0: n-limited (GEMM1), tf32-round output.  MODE 1: m-limited (GEMM2), plain output.
#define PAD 36
#define STGF ((128 + 256) * PAD)
#define NST 3
#define SMG (NST * STGF * 4)

template <int MODE>
__global__ __launch_bounds__(256, 1) void gemm_tc(
    const float* __restrict__ Aall, const float* __restrict__ Ball,
    float* __restrict__ Call,
    int K, int ldc, size_t bsA, size_t bsB, size_t bsC) {
    const int b = blockIdx.z;
    const int m0 = blockIdx.x * 128, n0 = blockIdx.y * 256;
    if (MODE == 0) { if (n0 >= g_Lcp256[b]) return; }
    else           { if (m0 >= g_Lcp128[b]) return; }

    extern __shared__ float sm[];
    const uint32_t smb = smem_u32(sm);
    const int tid = threadIdx.x, lane = tid & 31, wid = tid >> 5;
    const float* A = Aall + bsA * b;
    const float* Bp = Ball + bsB * b;
    float* C = Call + bsC * b;

    const int g = lane >> 2, t4 = lane & 3;
    const int warpM = wid & 1, warpN = wid >> 1;
    const int mrow0 = warpM * 64, ncol0 = warpN * 64;

    float acc[4][8][4];
#pragma unroll
    for (int mf = 0; mf < 4; mf++)
#pragma unroll
        for (int nf = 0; nf < 8; nf++)
#pragma unroll
            for (int j = 0; j < 4; j++) acc[mf][nf][j] = 0.f;

    auto load_stage = [&](int s, int ko) {
        const uint32_t sb = smb + (uint32_t)(s * STGF) * 4;
        {
            const int row = tid >> 1, kh = (tid & 1) * 16;
            const float* src = A + (size_t)(m0 + row) * K + ko + kh;
            const uint32_t dst = sb + (uint32_t)(row * PAD + kh) * 4;
#pragma unroll
            for (int j = 0; j < 4; j++) cpasync16(dst + j * 16, src + j * 4);
        }
        {
            const int row = tid;
            const float* src = Bp + (size_t)(n0 + row) * K + ko;
            const uint32_t dst = sb + (uint32_t)(128 * PAD + row * PAD) * 4;
#pragma unroll
            for (int j = 0; j < 8; j++) cpasync16(dst + j * 16, src + j * 4);
        }
    };

    const int NIT = K >> 5;
    load_stage(0, 0);  CP_COMMIT();
    load_stage(1, 32); CP_COMMIT();

    for (int i = 0; i < NIT; i++) {
        CP_WAIT1();
        __syncthreads();
        if (i + 2 < NIT) load_stage((i + 2) % NST, (i + 2) * 32);
        CP_COMMIT();

        const float* As = sm + (i % NST) * STGF;
        const float* Bs = As + 128 * PAD;
#pragma unroll
        for (int kk = 0; kk < 32; kk += 8) {
            uint32_t af[4][4];
#pragma unroll
            for (int mf = 0; mf < 4; mf++) {
                const float* ap = As + (mrow0 + mf * 16 + g) * PAD + kk + t4;
                af[mf][0] = ldr(ap);
                af[mf][1] = ldr(ap + 8 * PAD);
                af[mf][2] = ldr(ap + 4);
                af[mf][3] = ldr(ap + 8 * PAD + 4);
            }
#pragma unroll
            for (int nf = 0; nf < 8; nf++) {
                const float* bp = Bs + (ncol0 + nf * 8 + g) * PAD + kk + t4;
                const uint32_t b0 = ldr(bp), b1 = ldr(bp + 4);
#pragma unroll
                for (int mf = 0; mf < 4; mf++)
                    mma8(acc[mf][nf], af[mf][0], af[mf][1], af[mf][2], af[mf][3], b0, b1);
            }
        }
    }

#pragma unroll
    for (int mf = 0; mf < 4; mf++) {
        const int r0 = m0 + mrow0 + mf * 16 + g;
#pragma unroll
        for (int nf = 0; nf < 8; nf++) {
            const int c0 = n0 + ncol0 + nf * 8 + 2 * t4;
            float2 v0 = make_float2(acc[mf][nf][0], acc[mf][nf][1]);
            float2 v1 = make_float2(acc[mf][nf][2], acc[mf][nf][3]);
            if (MODE == 0) {
                v0.x = tf32r(v0.x); v0.y = tf32r(v0.y);
                v1.x = tf32r(v1.x); v1.y = tf32r(v1.y);
            }
            *(float2*)(C + (size_t)r0 * ldc + c0) = v0;
            *(float2*)(C + (size_t)(r0 + 8) * ldc + c0) = v1;
        }
    }
}

// ---------------- softmax on k rows over compact cols; zeroes g_ctx + pad ----------------
__global__ __launch_bounds__(256) void softmax_kernel() {
    const int b = blockIdx.y, r = blockIdx.x;
    const int tid = threadIdx.x;
    {
        const int gid = ((blockIdx.y * 1024 + blockIdx.x) << 8) + tid;
        if (gid < Bn * Hn * 64 * 64) g_ctx[gid] = 0.f;
    }
    const int lc = g_Lc[b], lcp = g_Lcp256[b];
    float* rowp = g_qkv + (size_t)b * O3 * Ln + (size_t)(1024 + r) * Ln;
    float sum = 0.f;
    for (int l = tid; l < lc; l += 256) sum += expf(rowp[l]);
    __shared__ float red[256];
    red[tid] = sum;
    __syncthreads();
    for (int s = 128; s > 0; s >>= 1) {
        if (tid < s) red[tid] += red[tid + s];
        __syncthreads();
    }
    const float inv = 1.f / red[0];
    for (int l = tid; l < lcp; l += 256)
        rowp[l] = (l < lc) ? tf32r(expf(rowp[l]) * inv) : 0.f;
}

// ---------------- context: chunks of 256 compact cols, diag blocks via atomicAdd ----------------
#define CSTGF (2 * 128 * PAD)
#define SMC (NST * CSTGF * 4)

__global__ __launch_bounds__(256, 1) void ctx_tc() {
    const int b = blockIdx.z, hp = blockIdx.x, ch = blockIdx.y;
    const int l0 = ch * 256;
    if (l0 >= g_Lcp256[b]) return;

    extern __shared__ float sm[];
    const uint32_t smb = smem_u32(sm);
    const int tid = threadIdx.x, lane = tid & 31, wid = tid >> 5;
    const float* A = g_qkv + (size_t)b * O3 * Ln + (size_t)(1024 + hp * 128) * Ln + l0;
    const float* Bp = g_qkv + (size_t)b * O3 * Ln + (size_t)(2048 + hp * 128) * Ln + l0;

    const int g = lane >> 2, t4 = lane & 3;
    const int warpM = wid & 1, warpN = wid >> 1;
    const int mrow0 = warpM * 64, ncol0 = warpN * 32;

    float acc[4][4][4];
#pragma unroll
    for (int mf = 0; mf < 4; mf++)
#pragma unroll
        for (int nf = 0; nf < 4; nf++)
#pragma unroll
            for (int j = 0; j < 4; j++) acc[mf][nf][j] = 0.f;

    auto load_stage = [&](int s, int ko) {
        const uint32_t sb = smb + (uint32_t)(s * CSTGF) * 4;
        const int row = tid >> 1, kh = (tid & 1) * 16;
        const float* srcA = A + (size_t)row * Ln + ko + kh;
        const float* srcB = Bp + (size_t)row * Ln + ko + kh;
        const uint32_t dA = sb + (uint32_t)(row * PAD + kh) * 4;
        const uint32_t dB = sb + (uint32_t)(128 * PAD + row * PAD + kh) * 4;
#pragma unroll
        for (int j = 0; j < 4; j++) {
            cpasync16(dA + j * 16, srcA + j * 4);
            cpasync16(dB + j * 16, srcB + j * 4);
        }
    };

    const int NIT = 8;   // 256 / 32
    load_stage(0, 0);  CP_COMMIT();
    load_stage(1, 32); CP_COMMIT();

    for (int i = 0; i < NIT; i++) {
        CP_WAIT1();
        __syncthreads();
        if (i + 2 < NIT) load_stage((i + 2) % NST, (i + 2) * 32);
        CP_COMMIT();

        const float* As = sm + (i % NST) * CSTGF;
        const float* Bs = As + 128 * PAD;
#pragma unroll
        for (int kk = 0; kk < 32; kk += 8) {
            uint32_t af[4][4];
#pragma unroll
            for (int mf = 0; mf < 4; mf++) {
                const float* ap = As + (mrow0 + mf * 16 + g) * PAD + kk + t4;
                af[mf][0] = ldr(ap);
                af[mf][1] = ldr(ap + 8 * PAD);
                af[mf][2] = ldr(ap + 4);
                af[mf][3] = ldr(ap + 8 * PAD + 4);
            }
#pragma unroll
            for (int nf = 0; nf < 4; nf++) {
                const float* bp = Bs + (ncol0 + nf * 8 + g) * PAD + kk + t4;
                const uint32_t b0 = ldr(bp), b1 = ldr(bp + 4);
#pragma unroll
                for (int mf = 0; mf < 4; mf++)
                    mma8(acc[mf][nf], af[mf][0], af[mf][1], af[mf][2], af[mf][3], b0, b1);
            }
        }
    }

    if (warpM == (warpN >> 1)) {
        const int h = hp * 2 + warpM;
        float* cp = g_ctx + (size_t)(b * Hn + h) * 64 * 64;
#pragma unroll
        for (int mf = 0; mf < 4; mf++) {
            const int d0 = mf * 16 + g;
#pragma unroll
            for (int nf = 0; nf < 4; nf++) {
                const int e0 = (warpN & 1) * 32 + nf * 8 + 2 * t4;
                atomicAdd(cp + (size_t)d0 * 64 + e0, acc[mf][nf][0]);
                atomicAdd(cp + (size_t)d0 * 64 + e0 + 1, acc[mf][nf][1]);
                atomicAdd(cp + (size_t)(d0 + 8) * 64 + e0, acc[mf][nf][2]);
                atomicAdd(cp + (size_t)(d0 + 8) * 64 + e0 + 1, acc[mf][nf][3]);
            }
        }
    }
}

// ---------------- weff (SIMT, f32 in, tf32 out) ----------------
__global__ __launch_bounds__(256) void weff_kernel(const float* __restrict__ wout) {
    __shared__ float Ws[64][65];
    __shared__ float Cs[64][68];
    const int b = blockIdx.z, h = blockIdx.y, o0 = blockIdx.x * 64;
    const int tid = threadIdx.x;
    const int rr = tid >> 2;
    const int q4 = (tid & 3) * 16;
    const float* wp = wout + (size_t)(o0 + rr) * Dn + h * 64 + q4;
#pragma unroll
    for (int j = 0; j < 16; j += 4) {
        float4 t4v = *(const float4*)(wp + j);
        Ws[q4 + j + 0][rr] = t4v.x; Ws[q4 + j + 1][rr] = t4v.y;
        Ws[q4 + j + 2][rr] = t4v.z; Ws[q4 + j + 3][rr] = t4v.w;
    }
    const float* cp = g_ctx + ((size_t)(b * Hn + h) * 64 + rr) * 64 + q4;
#pragma unroll
    for (int j = 0; j < 16; j += 4) *(float4*)&Cs[rr][q4 + j] = *(const float4*)(cp + j);
    __syncthreads();

    const int oo = tid >> 2, eg = tid & 3;
    float acc[16];
#pragma unroll
    for (int j = 0; j < 16; j++) acc[j] = 0.f;
#pragma unroll 8
    for (int dd = 0; dd < 64; dd++) {
        const float wv = Ws[dd][oo];
#pragma unroll
        for (int j = 0; j < 16; j++) acc[j] = fmaf(wv, Cs[dd][eg * 16 + j], acc[j]);
    }
    float* op = g_weff + (size_t)b * Dn * Dn + (size_t)(o0 + oo) * Dn + h * 64 + eg * 16;
#pragma unroll
    for (int j = 0; j < 16; j += 4)
        *(float4*)(op + j) = make_float4(tf32r(acc[j]), tf32r(acc[j + 1]),
                                         tf32r(acc[j + 2]), tf32r(acc[j + 3]));
}

// ---------------- transpose q -> qT (compact rows, 0.125 scale) ----------------
__global__ __launch_bounds__(256) void transpose_q() {
    const int b = blockIdx.z, l0 = blockIdx.x * 32, c0 = blockIdx.y * 32;
    if (l0 >= g_Lcp128[b]) return;
    __shared__ float t[32][33];
    const int tx = threadIdx.x & 31, ty = threadIdx.x >> 5;
    const float* q = g_qkv + (size_t)b * O3 * Ln;
#pragma unroll
    for (int k = 0; k < 4; k++)
        t[ty + 8 * k][tx] = q[(size_t)(c0 + ty + 8 * k) * Ln + l0 + tx];
    __syncthreads();
#pragma unroll
    for (int k = 0; k < 4; k++) {
        const int l = l0 + ty + 8 * k;
        g_qT[((size_t)b * Ln + l) * Dn + c0 + tx] = 0.125f * t[tx][ty + 8 * k];
    }
}

// ---------------- scatter: out[b,l,:] = (unmasked ? outc[rank] : 0) + b_out ----------------
__global__ __launch_bounds__(256) void scatter_kernel(const float4* __restrict__ bout,
                                                      float4* __restrict__ out) {
    const int b = blockIdx.y, l = blockIdx.x, tid = threadIdx.x;
    const int r = g_rank[b][l];
    float4 bb = bout[tid];
    if (r >= 0) {
        float4 v = ((const float4*)g_outc)[((size_t)b * Ln + r) * 256 + tid];
        bb.x += v.x; bb.y += v.y; bb.z += v.z; bb.w += v.w;
    }
    out[((size_t)b * Ln + l) * 256 + tid] = bb;
}

// ---------------- host side ----------------
extern "C" void kernel_launch(void* const* d_in, const int* in_sizes, int n_in,
                              void* d_out, int out_size) {
    const float* x = (const float*)d_in[0];
    const void* masks = d_in[1];
    const float* w_qkv = (const float*)d_in[2];
    const float* w_out = (const float*)d_in[3];
    const float* b_out = (const float*)d_in[4];
    float* out = (float*)d_out;

    void *pQ, *pQT, *pWE, *pX, *pW, *pOC;
    cudaGetSymbolAddress(&pQ, g_qkv);
    cudaGetSymbolAddress(&pQT, g_qT);
    cudaGetSymbolAddress(&pWE, g_weff);
    cudaGetSymbolAddress(&pX, g_x32);
    cudaGetSymbolAddress(&pW, g_w32);
    cudaGetSymbolAddress(&pOC, g_outc);

    cudaFuncSetAttribute(gemm_tc<0>, cudaFuncAttributeMaxDynamicSharedMemorySize, SMG);
    cudaFuncSetAttribute(gemm_tc<1>, cudaFuncAttributeMaxDynamicSharedMemorySize, SMG);
    cudaFuncSetAttribute(ctx_tc, cudaFuncAttributeMaxDynamicSharedMemorySize, SMC);

    detect_mask_kernel<<<1, 256>>>((const unsigned char*)masks);
    count_kernel<<<Bn, 256>>>(masks);
    prep_w<<<O3, 256>>>((const float4*)w_qkv);
    prep_x<<<dim3(Ln, Bn), 256>>>((const float4*)x);

    // GEMM1: g_qkv[b](3072 x Lcp) = g_w32 @ g_x32[b]^T
    gemm_tc<0><<<dim3(24, 16, Bn), 256, SMG>>>(
        (const float*)pW, (const float*)pX, (float*)pQ,
        Dn, Ln, (size_t)0, (size_t)Ln * Dn, (size_t)O3 * Ln);

    softmax_kernel<<<dim3(1024, Bn), 256>>>();

    ctx_tc<<<dim3(8, 16, Bn), 256, SMC>>>();

    weff_kernel<<<dim3(16, Hn, Bn), 256>>>(w_out);

    transpose_q<<<dim3(128, 32, Bn), 256>>>();

    // GEMM2: g_outc[b](Lcp2 x 1024) = g_qT[b] @ g_weff[b]^T
    gemm_tc<1><<<dim3(32, 4, Bn), 256, SMG>>>(
        (const float*)pQT, (const float*)pWE, (float*)pOC,
        Dn, Dn, (size_t)Ln * Dn, (size_t)Dn * Dn, (size_t)Ln * Dn);

    scatter_kernel<<<dim3(Ln, Bn), 256>>>((const float4*)b_out, (float4*)out);
}

// round 7
// speedup vs baseline: 4.4656x; 1.0760x over previous
#include <cuda_runtime.h>
#include <math.h>
#include <cstdint>

#define Bn 8
#define Ln 4096
#define Dn 1024
#define Hn 16
#define O3 3072

// ---------------- scratch (static device globals; no allocation) ----------------
__device__ __align__(256) float g_qkv[(size_t)Bn * O3 * Ln];   // (B,3072,L) tf32, compact cols
__device__ __align__(256) float g_qT[(size_t)Bn * Ln * Dn];    // (B,Lc,1024) tf32
__device__ __align__(256) float g_x32[(size_t)Bn * Ln * Dn];   // compacted+rounded x
__device__ __align__(256) float g_w32[(size_t)O3 * Dn];        // rounded w_qkv
__device__ __align__(256) float g_ctx[Bn * Hn * 64 * 64];
__device__ __align__(256) float g_weff[(size_t)Bn * Dn * Dn];
__device__ int g_idx[Bn][Ln];    // compact j -> original l
__device__ int g_rank[Bn][Ln];   // original l -> compact j or -1
__device__ int g_Lc[Bn];         // unmasked count
__device__ int g_Lcp256[Bn];     // padded to 256
__device__ int g_Lcp128[Bn];     // padded to 128
__device__ int g_mask_u8;

// ---------------- helpers ----------------
__device__ __forceinline__ uint32_t smem_u32(const void* p) {
    uint32_t a;
    asm("{ .reg .u64 t; cvta.to.shared.u64 t, %1; cvt.u32.u64 %0, t; }" : "=r"(a) : "l"(p));
    return a;
}
__device__ __forceinline__ float tf32r(float v) {
    uint32_t o;
    asm("cvt.rna.tf32.f32 %0, %1;" : "=r"(o) : "f"(v));
    return __uint_as_float(o);
}
__device__ __forceinline__ void cpasync16(uint32_t dst, const void* src) {
    asm volatile("cp.async.cg.shared.global [%0], [%1], 16;" :: "r"(dst), "l"(src) : "memory");
}
#define CP_COMMIT() asm volatile("cp.async.commit_group;" ::: "memory")
#define CP_WAIT1()  asm volatile("cp.async.wait_group 1;" ::: "memory")

__device__ __forceinline__ void mma8(float* c, uint32_t a0, uint32_t a1, uint32_t a2, uint32_t a3,
                                     uint32_t b0, uint32_t b1) {
    asm volatile("mma.sync.aligned.m16n8k8.row.col.f32.tf32.tf32.f32 "
        "{%0,%1,%2,%3}, {%4,%5,%6,%7}, {%8,%9}, {%0,%1,%2,%3};"
        : "+f"(c[0]), "+f"(c[1]), "+f"(c[2]), "+f"(c[3])
        : "r"(a0), "r"(a1), "r"(a2), "r"(a3), "r"(b0), "r"(b1));
}
__device__ __forceinline__ bool mask_at(const void* m, int idx, int u8) {
    if (u8) return ((const unsigned char*)m)[idx] != 0;
    return ((const int*)m)[idx] != 0;
}
__device__ __forceinline__ uint32_t ldr(const float* p) { return __float_as_uint(*p); }

// ---------------- mask detect + compaction maps ----------------
__global__ void detect_mask_kernel(const unsigned char* __restrict__ m) {
    __shared__ int found;
    if (threadIdx.x == 0) found = 0;
    __syncthreads();
    int local = 0;
    for (int i = threadIdx.x; i < 4096; i += blockDim.x)
        if ((i & 3) && m[i]) local = 1;
    if (local) atomicOr(&found, 1);
    __syncthreads();
    if (threadIdx.x == 0) g_mask_u8 = found;
}

__global__ __launch_bounds__(256) void count_kernel(const void* __restrict__ mask) {
    const int b = blockIdx.x, tid = threadIdx.x;
    const int u8 = g_mask_u8;
    __shared__ int cnt[256];
    __shared__ int excl[257];
    int loc[16], c = 0;
#pragma unroll
    for (int t = 0; t < 16; t++) {
        const int l = tid * 16 + t;
        loc[t] = mask_at(mask, b * Ln + l, u8) ? 0 : 1;
        c += loc[t];
    }
    cnt[tid] = c;
    __syncthreads();
    if (tid == 0) {
        int s = 0;
        for (int i = 0; i < 256; i++) { excl[i] = s; s += cnt[i]; }
        excl[256] = s;
        g_Lc[b] = s;
        g_Lcp256[b] = (s + 255) & ~255;
        g_Lcp128[b] = (s + 127) & ~127;
    }
    __syncthreads();
    int j = excl[tid];
#pragma unroll
    for (int t = 0; t < 16; t++) {
        const int l = tid * 16 + t;
        if (loc[t]) { g_idx[b][j] = l; g_rank[b][l] = j; j++; }
        else g_rank[b][l] = -1;
    }
}

// ---------------- prep: rounded w; compacted+rounded x (zero pad) ----------------
__global__ __launch_bounds__(256) void prep_w(const float4* __restrict__ w) {
    const int r = blockIdx.x, tid = threadIdx.x;
    float4 v = w[(size_t)r * 256 + tid];
    v.x = tf32r(v.x); v.y = tf32r(v.y); v.z = tf32r(v.z); v.w = tf32r(v.w);
    ((float4*)g_w32)[(size_t)r * 256 + tid] = v;
}

__global__ __launch_bounds__(256) void prep_x(const float4* __restrict__ x) {
    const int b = blockIdx.y, j = blockIdx.x, tid = threadIdx.x;
    if (j >= g_Lcp256[b]) return;
    float4* dst = (float4*)g_x32 + ((size_t)b * Ln + j) * 256;
    if (j >= g_Lc[b]) { dst[tid] = make_float4(0.f, 0.f, 0.f, 0.f); return; }
    const int l = g_idx[b][j];
    float4 v = x[((size_t)b * Ln + l) * 256 + tid];
    v.x = tf32r(v.x); v.y = tf32r(v.y); v.z = tf32r(v.z); v.w = tf32r(v.w);
    dst[tid] = v;
}

// ---------------- GEMM: C(M x N) = A(M x K) @ B(N x K)^T, tiles 128x128x32, 2 CTA/SM ----------------
// MODE 0: n-limited (GEMM1), tf32-round output to C.
// MODE 1: m-limited (GEMM2), bias + scatter rows via g_idx into C (= final out).
#define PAD 36
#define STGF ((128 + 128) * PAD)   // 9216 floats / stage
#define NST 3
#define SMG (NST * STGF * 4)       // 110592 B

template <int MODE>
__global__ __launch_bounds__(256, 2) void gemm_tc(
    const float* __restrict__ Aall, const float* __restrict__ Ball,
    float* __restrict__ Call, const float* __restrict__ bias,
    int K, int ldc, size_t bsA, size_t bsB, size_t bsC) {
    const int b = blockIdx.z;
    const int m0 = blockIdx.x * 128, n0 = blockIdx.y * 128;
    if (MODE == 0) { if (n0 >= g_Lcp128[b]) return; }
    else           { if (m0 >= g_Lcp128[b]) return; }

    extern __shared__ float sm[];
    const uint32_t smb = smem_u32(sm);
    const int tid = threadIdx.x, lane = tid & 31, wid = tid >> 5;
    const float* A = Aall + bsA * b;
    const float* Bp = Ball + bsB * b;
    float* C = Call + bsC * b;

    const int g = lane >> 2, t4 = lane & 3;
    const int warpM = wid & 1, warpN = wid >> 1;      // 2 x 4 warps
    const int mrow0 = warpM * 64, ncol0 = warpN * 32; // warp tile 64 x 32

    float acc[4][4][4];
#pragma unroll
    for (int mf = 0; mf < 4; mf++)
#pragma unroll
        for (int nf = 0; nf < 4; nf++)
#pragma unroll
            for (int j = 0; j < 4; j++) acc[mf][nf][j] = 0.f;

    auto load_stage = [&](int s, int ko) {
        const uint32_t sb = smb + (uint32_t)(s * STGF) * 4;
        const int row = tid >> 1, kh = (tid & 1) * 16;
        const float* srcA = A + (size_t)(m0 + row) * K + ko + kh;
        const float* srcB = Bp + (size_t)(n0 + row) * K + ko + kh;
        const uint32_t dA = sb + (uint32_t)(row * PAD + kh) * 4;
        const uint32_t dB = sb + (uint32_t)((128 + row) * PAD + kh) * 4;
#pragma unroll
        for (int j = 0; j < 4; j++) {
            cpasync16(dA + j * 16, srcA + j * 4);
            cpasync16(dB + j * 16, srcB + j * 4);
        }
    };

    const int NIT = K >> 5;
    load_stage(0, 0);  CP_COMMIT();
    load_stage(1, 32); CP_COMMIT();

    for (int i = 0; i < NIT; i++) {
        CP_WAIT1();
        __syncthreads();
        if (i + 2 < NIT) load_stage((i + 2) % NST, (i + 2) * 32);
        CP_COMMIT();

        const float* As = sm + (i % NST) * STGF;
        const float* Bs = As + 128 * PAD;
#pragma unroll
        for (int kk = 0; kk < 32; kk += 8) {
            uint32_t af[4][4];
#pragma unroll
            for (int mf = 0; mf < 4; mf++) {
                const float* ap = As + (mrow0 + mf * 16 + g) * PAD + kk + t4;
                af[mf][0] = ldr(ap);
                af[mf][1] = ldr(ap + 8 * PAD);
                af[mf][2] = ldr(ap + 4);
                af[mf][3] = ldr(ap + 8 * PAD + 4);
            }
#pragma unroll
            for (int nf = 0; nf < 4; nf++) {
                const float* bp = Bs + (ncol0 + nf * 8 + g) * PAD + kk + t4;
                const uint32_t b0 = ldr(bp), b1 = ldr(bp + 4);
#pragma unroll
                for (int mf = 0; mf < 4; mf++)
                    mma8(acc[mf][nf], af[mf][0], af[mf][1], af[mf][2], af[mf][3], b0, b1);
            }
        }
    }

    if (MODE == 0) {
#pragma unroll
        for (int mf = 0; mf < 4; mf++) {
            const int r0 = m0 + mrow0 + mf * 16 + g;
#pragma unroll
            for (int nf = 0; nf < 4; nf++) {
                const int c0 = n0 + ncol0 + nf * 8 + 2 * t4;
                float2 v0 = make_float2(tf32r(acc[mf][nf][0]), tf32r(acc[mf][nf][1]));
                float2 v1 = make_float2(tf32r(acc[mf][nf][2]), tf32r(acc[mf][nf][3]));
                *(float2*)(C + (size_t)r0 * ldc + c0) = v0;
                *(float2*)(C + (size_t)(r0 + 8) * ldc + c0) = v1;
            }
        }
    } else {
        const int lc = g_Lc[b];
#pragma unroll
        for (int mf = 0; mf < 4; mf++) {
            const int r0 = m0 + mrow0 + mf * 16 + g;
            const int la = (r0 < lc) ? g_idx[b][r0] : -1;
            const int lb2 = (r0 + 8 < lc) ? g_idx[b][r0 + 8] : -1;
#pragma unroll
            for (int nf = 0; nf < 4; nf++) {
                const int c0 = n0 + ncol0 + nf * 8 + 2 * t4;
                const float2 bb = *(const float2*)(bias + c0);
                if (la >= 0) {
                    float2 v0 = make_float2(acc[mf][nf][0] + bb.x, acc[mf][nf][1] + bb.y);
                    *(float2*)(C + ((size_t)b * 0 + (size_t)la) * ldc + c0) = v0;
                }
                if (lb2 >= 0) {
                    float2 v1 = make_float2(acc[mf][nf][2] + bb.x, acc[mf][nf][3] + bb.y);
                    *(float2*)(C + (size_t)lb2 * ldc + c0) = v1;
                }
            }
        }
    }
}

// ---------------- fill masked rows of out with bias ----------------
__global__ __launch_bounds__(256) void fill_bias(const float4* __restrict__ bout,
                                                 float4* __restrict__ out) {
    const int b = blockIdx.y, l = blockIdx.x, tid = threadIdx.x;
    if (g_rank[b][l] >= 0) return;
    out[((size_t)b * Ln + l) * 256 + tid] = bout[tid];
}

// ---------------- softmax on k rows over compact cols; zeroes g_ctx + pad ----------------
__global__ __launch_bounds__(256) void softmax_kernel() {
    const int b = blockIdx.y, r = blockIdx.x;
    const int tid = threadIdx.x;
    {
        const int gid = ((blockIdx.y * 1024 + blockIdx.x) << 8) + tid;
        if (gid < Bn * Hn * 64 * 64) g_ctx[gid] = 0.f;
    }
    const int lc = g_Lc[b], lcp = g_Lcp256[b];
    float* rowp = g_qkv + (size_t)b * O3 * Ln + (size_t)(1024 + r) * Ln;
    float sum = 0.f;
    for (int l = tid; l < lc; l += 256) sum += expf(rowp[l]);
    __shared__ float red[256];
    red[tid] = sum;
    __syncthreads();
    for (int s = 128; s > 0; s >>= 1) {
        if (tid < s) red[tid] += red[tid + s];
        __syncthreads();
    }
    const float inv = 1.f / red[0];
    for (int l = tid; l < lcp; l += 256)
        rowp[l] = (l < lc) ? tf32r(expf(rowp[l]) * inv) : 0.f;
}

// ---------------- context: chunks of 256 compact cols, diag blocks via atomicAdd ----------------
#define CSTGF (2 * 128 * PAD)
#define SMC (NST * CSTGF * 4)   // 110592 B

__global__ __launch_bounds__(256, 2) void ctx_tc() {
    const int b = blockIdx.z, hp = blockIdx.x, ch = blockIdx.y;
    const int l0 = ch * 256;
    if (l0 >= g_Lcp256[b]) return;

    extern __shared__ float sm[];
    const uint32_t smb = smem_u32(sm);
    const int tid = threadIdx.x, lane = tid & 31, wid = tid >> 5;
    const float* A = g_qkv + (size_t)b * O3 * Ln + (size_t)(1024 + hp * 128) * Ln + l0;
    const float* Bp = g_qkv + (size_t)b * O3 * Ln + (size_t)(2048 + hp * 128) * Ln + l0;

    const int g = lane >> 2, t4 = lane & 3;
    const int warpM = wid & 1, warpN = wid >> 1;
    const int mrow0 = warpM * 64, ncol0 = warpN * 32;

    float acc[4][4][4];
#pragma unroll
    for (int mf = 0; mf < 4; mf++)
#pragma unroll
        for (int nf = 0; nf < 4; nf++)
#pragma unroll
            for (int j = 0; j < 4; j++) acc[mf][nf][j] = 0.f;

    auto load_stage = [&](int s, int ko) {
        const uint32_t sb = smb + (uint32_t)(s * CSTGF) * 4;
        const int row = tid >> 1, kh = (tid & 1) * 16;
        const float* srcA = A + (size_t)row * Ln + ko + kh;
        const float* srcB = Bp + (size_t)row * Ln + ko + kh;
        const uint32_t dA = sb + (uint32_t)(row * PAD + kh) * 4;
        const uint32_t dB = sb + (uint32_t)(128 * PAD + row * PAD + kh) * 4;
#pragma unroll
        for (int j = 0; j < 4; j++) {
            cpasync16(dA + j * 16, srcA + j * 4);
            cpasync16(dB + j * 16, srcB + j * 4);
        }
    };

    const int NIT = 8;   // 256 / 32
    load_stage(0, 0);  CP_COMMIT();
    load_stage(1, 32); CP_COMMIT();

    for (int i = 0; i < NIT; i++) {
        CP_WAIT1();
        __syncthreads();
        if (i + 2 < NIT) load_stage((i + 2) % NST, (i + 2) * 32);
        CP_COMMIT();

        const float* As = sm + (i % NST) * CSTGF;
        const float* Bs = As + 128 * PAD;
#pragma unroll
        for (int kk = 0; kk < 32; kk += 8) {
            uint32_t af[4][4];
#pragma unroll
            for (int mf = 0; mf < 4; mf++) {
                const float* ap = As + (mrow0 + mf * 16 + g) * PAD + kk + t4;
                af[mf][0] = ldr(ap);
                af[mf][1] = ldr(ap + 8 * PAD);
                af[mf][2] = ldr(ap + 4);
                af[mf][3] = ldr(ap + 8 * PAD + 4);
            }
#pragma unroll
            for (int nf = 0; nf < 4; nf++) {
                const float* bp = Bs + (ncol0 + nf * 8 + g) * PAD + kk + t4;
                const uint32_t b0 = ldr(bp), b1 = ldr(bp + 4);
#pragma unroll
                for (int mf = 0; mf < 4; mf++)
                    mma8(acc[mf][nf], af[mf][0], af[mf][1], af[mf][2], af[mf][3], b0, b1);
            }
        }
    }

    if (warpM == (warpN >> 1)) {
        const int h = hp * 2 + warpM;
        float* cp = g_ctx + (size_t)(b * Hn + h) * 64 * 64;
#pragma unroll
        for (int mf = 0; mf < 4; mf++) {
            const int d0 = mf * 16 + g;
#pragma unroll
            for (int nf = 0; nf < 4; nf++) {
                const int e0 = (warpN & 1) * 32 + nf * 8 + 2 * t4;
                atomicAdd(cp + (size_t)d0 * 64 + e0, acc[mf][nf][0]);
                atomicAdd(cp + (size_t)d0 * 64 + e0 + 1, acc[mf][nf][1]);
                atomicAdd(cp + (size_t)(d0 + 8) * 64 + e0, acc[mf][nf][2]);
                atomicAdd(cp + (size_t)(d0 + 8) * 64 + e0 + 1, acc[mf][nf][3]);
            }
        }
    }
}

// ---------------- weff (SIMT, f32 in, tf32 out) ----------------
__global__ __launch_bounds__(256) void weff_kernel(const float* __restrict__ wout) {
    __shared__ float Ws[64][65];
    __shared__ float Cs[64][68];
    const int b = blockIdx.z, h = blockIdx.y, o0 = blockIdx.x * 64;
    const int tid = threadIdx.x;
    const int rr = tid >> 2;
    const int q4 = (tid & 3) * 16;
    const float* wp = wout + (size_t)(o0 + rr) * Dn + h * 64 + q4;
#pragma unroll
    for (int j = 0; j < 16; j += 4) {
        float4 t4v = *(const float4*)(wp + j);
        Ws[q4 + j + 0][rr] = t4v.x; Ws[q4 + j + 1][rr] = t4v.y;
        Ws[q4 + j + 2][rr] = t4v.z; Ws[q4 + j + 3][rr] = t4v.w;
    }
    const float* cp = g_ctx + ((size_t)(b * Hn + h) * 64 + rr) * 64 + q4;
#pragma unroll
    for (int j = 0; j < 16; j += 4) *(float4*)&Cs[rr][q4 + j] = *(const float4*)(cp + j);
    __syncthreads();

    const int oo = tid >> 2, eg = tid & 3;
    float acc[16];
#pragma unroll
    for (int j = 0; j < 16; j++) acc[j] = 0.f;
#pragma unroll 8
    for (int dd = 0; dd < 64; dd++) {
        const float wv = Ws[dd][oo];
#pragma unroll
        for (int j = 0; j < 16; j++) acc[j] = fmaf(wv, Cs[dd][eg * 16 + j], acc[j]);
    }
    float* op = g_weff + (size_t)b * Dn * Dn + (size_t)(o0 + oo) * Dn + h * 64 + eg * 16;
#pragma unroll
    for (int j = 0; j < 16; j += 4)
        *(float4*)(op + j) = make_float4(tf32r(acc[j]), tf32r(acc[j + 1]),
                                         tf32r(acc[j + 2]), tf32r(acc[j + 3]));
}

// ---------------- transpose q -> qT (compact rows, 0.125 scale) ----------------
__global__ __launch_bounds__(256) void transpose_q() {
    const int b = blockIdx.z, l0 = blockIdx.x * 32, c0 = blockIdx.y * 32;
    if (l0 >= g_Lcp128[b]) return;
    __shared__ float t[32][33];
    const int tx = threadIdx.x & 31, ty = threadIdx.x >> 5;
    const float* q = g_qkv + (size_t)b * O3 * Ln;
#pragma unroll
    for (int k = 0; k < 4; k++)
        t[ty + 8 * k][tx] = q[(size_t)(c0 + ty + 8 * k) * Ln + l0 + tx];
    __syncthreads();
#pragma unroll
    for (int k = 0; k < 4; k++) {
        const int l = l0 + ty + 8 * k;
        g_qT[((size_t)b * Ln + l) * Dn + c0 + tx] = 0.125f * t[tx][ty + 8 * k];
    }
}

// ---------------- host side ----------------
extern "C" void kernel_launch(void* const* d_in, const int* in_sizes, int n_in,
                              void* d_out, int out_size) {
    const float* x = (const float*)d_in[0];
    const void* masks = d_in[1];
    const float* w_qkv = (const float*)d_in[2];
    const float* w_out = (const float*)d_in[3];
    const float* b_out = (const float*)d_in[4];
    float* out = (float*)d_out;

    void *pQ, *pQT, *pWE, *pX, *pW;
    cudaGetSymbolAddress(&pQ, g_qkv);
    cudaGetSymbolAddress(&pQT, g_qT);
    cudaGetSymbolAddress(&pWE, g_weff);
    cudaGetSymbolAddress(&pX, g_x32);
    cudaGetSymbolAddress(&pW, g_w32);

    cudaFuncSetAttribute(gemm_tc<0>, cudaFuncAttributeMaxDynamicSharedMemorySize, SMG);
    cudaFuncSetAttribute(gemm_tc<1>, cudaFuncAttributeMaxDynamicSharedMemorySize, SMG);
    cudaFuncSetAttribute(ctx_tc, cudaFuncAttributeMaxDynamicSharedMemorySize, SMC);

    detect_mask_kernel<<<1, 256>>>((const unsigned char*)masks);
    count_kernel<<<Bn, 256>>>(masks);
    prep_w<<<O3, 256>>>((const float4*)w_qkv);
    prep_x<<<dim3(Ln, Bn), 256>>>((const float4*)x);
    fill_bias<<<dim3(Ln, Bn), 256>>>((const float4*)b_out, (float4*)out);

    // GEMM1: g_qkv[b](3072 x Lcp) = g_w32 @ g_x32[b]^T
    gemm_tc<0><<<dim3(24, 32, Bn), 256, SMG>>>(
        (const float*)pW, (const float*)pX, (float*)pQ, nullptr,
        Dn, Ln, (size_t)0, (size_t)Ln * Dn, (size_t)O3 * Ln);

    softmax_kernel<<<dim3(1024, Bn), 256>>>();

    ctx_tc<<<dim3(8, 16, Bn), 256, SMC>>>();

    weff_kernel<<<dim3(16, Hn, Bn), 256>>>(w_out);

    transpose_q<<<dim3(128, 32, Bn), 256>>>();

    // GEMM2: out rows (scattered via g_idx) = g_qT[b] @ g_weff[b]^T + b_out
    gemm_tc<1><<<dim3(32, 8, Bn), 256, SMG>>>(
        (const float*)pQT, (const float*)pWE, out + 0, b_out,
        Dn, Dn, (size_t)Ln * Dn, (size_t)Dn * Dn, (size_t)Ln * Dn);

    // note: MODE 1 epilogue indexes C with absolute row (b*Ln + l) already folded:
    // C = out + b*bsC, rows written at l*ldc -> out[(b*Ln + l)*Dn] since bsC = Ln*Dn.
}